// round 10
// baseline (speedup 1.0000x reference)
#include <cuda_runtime.h>
#include <cuda_bf16.h>
#include <cuda_fp16.h>
#include <math.h>
#include <stdint.h>

#define NB 4
#define NN 4096
#define CCH 8
#define WCHUNK 64

typedef unsigned long long ull;

__device__ __forceinline__ uint32_t s2u(const void* p){
    uint32_t a;
    asm("{ .reg .u64 t; cvta.to.shared.u64 t, %1; cvt.u32.u64 %0, t; }" : "=r"(a) : "l"(p));
    return a;
}
__device__ __forceinline__ void cpasync16(uint32_t dst, const void* src){
    asm volatile("cp.async.cg.shared.global [%0], [%1], 16;" :: "r"(dst), "l"(src));
}
#define CP_COMMIT() asm volatile("cp.async.commit_group;" ::: "memory")

__device__ __forceinline__ void ldmx4(uint32_t& r0, uint32_t& r1, uint32_t& r2, uint32_t& r3, uint32_t a){
    asm volatile("ldmatrix.sync.aligned.m8n8.x4.shared.b16 {%0,%1,%2,%3}, [%4];"
        : "=r"(r0), "=r"(r1), "=r"(r2), "=r"(r3) : "r"(a));
}
__device__ __forceinline__ void ldmx2(uint32_t& r0, uint32_t& r1, uint32_t a){
    asm volatile("ldmatrix.sync.aligned.m8n8.x2.shared.b16 {%0,%1}, [%2];"
        : "=r"(r0), "=r"(r1) : "r"(a));
}
__device__ __forceinline__ void mma16816(float* d, uint32_t a0, uint32_t a1, uint32_t a2, uint32_t a3,
                                         uint32_t b0, uint32_t b1){
    asm volatile("mma.sync.aligned.m16n8k16.row.col.f32.bf16.bf16.f32 "
        "{%0,%1,%2,%3}, {%4,%5,%6,%7}, {%8,%9}, {%0,%1,%2,%3};"
        : "+f"(d[0]), "+f"(d[1]), "+f"(d[2]), "+f"(d[3])
        : "r"(a0), "r"(a1), "r"(a2), "r"(a3), "r"(b0), "r"(b1));
}
__device__ __forceinline__ void mma16816h(float* d, uint32_t a0, uint32_t a1, uint32_t a2, uint32_t a3,
                                          uint32_t b0, uint32_t b1){
    asm volatile("mma.sync.aligned.m16n8k16.row.col.f32.f16.f16.f32 "
        "{%0,%1,%2,%3}, {%4,%5,%6,%7}, {%8,%9}, {%0,%1,%2,%3};"
        : "+f"(d[0]), "+f"(d[1]), "+f"(d[2]), "+f"(d[3])
        : "r"(a0), "r"(a1), "r"(a2), "r"(a3), "r"(b0), "r"(b1));
}
__device__ __forceinline__ uint32_t cvtpack(float hi, float lo){
    uint32_t r; asm("cvt.rn.bf16x2.f32 %0, %1, %2;" : "=r"(r) : "f"(hi), "f"(lo)); return r;
}
__device__ __forceinline__ uint32_t cvtpackh(float hi, float lo){
    uint32_t r; asm("cvt.rn.f16x2.f32 %0, %1, %2;" : "=r"(r) : "f"(hi), "f"(lo)); return r;
}

// ---------------- device global scratch ----------------
__device__ float g_w3j[14][2197];
__device__ double g_psum[14][WCHUNK];
__device__ float g_M[8][3];
__device__ float g_rv[NB][NN][68];                 // 66 used
__device__ float g_ctx[NB][NN][68];                // 66 used
__device__ __nv_bfloat16 g_fqh[NB][NN][32];        // query feats hi (22 + feat22=1)
__device__ __nv_bfloat16 g_fql[NB][NN][32];        // query feats lo
__device__ __nv_bfloat16 g_fkh[NB][NN][32];        // key feats hi (22 + feat22=pb)
__device__ __nv_bfloat16 g_fkl[NB][NN][32];        // key feats lo
__device__ __half g_rvTh[NB][72][NN];              // transposed V fp16, row 66 = ones

__constant__ int c_VAL_L[6][3] = {{4,0,4},{4,2,4},{6,2,4},{4,2,6},{6,0,6},{6,2,6}};
__constant__ int c_OUT_L[8][3] = {{4,4,4},{4,6,4},{6,4,4},{6,6,4},{4,4,6},{4,6,6},{6,4,6},{6,6,6}};
__constant__ int c_OUT_OFF[8] = {0,729,1782,2835,4356,5409,6930,8451};
__constant__ int c_VAL_OFF[6] = {0,81,486,1071,1656,1825};
__constant__ int c_VAL_SZ[6]  = {81,405,585,585,169,845};
__constant__ int c_OUT_SZ[8]  = {729,1053,1053,1521,1053,1521,1521,2197};
__constant__ unsigned char c_T2P[66] = {
    0,0,0,0,0,0,0,0,0, 1,1,1,1,1,1,1,1,1, 2,2,2,2,2,2,2,2,2,
    3,3,3,3,3,3,3,3,3,3,3,3,3, 4,4,4,4,4,4,4,4,4,4,4,4,4, 5,5,5,5,5,5,5,5,5,5,5,5,5};
__constant__ unsigned char c_T2K[66] = {
    0,1,2,3,4,5,6,7,8, 0,1,2,3,4,5,6,7,8, 0,1,2,3,4,5,6,7,8,
    0,1,2,3,4,5,6,7,8,9,10,11,12, 0,1,2,3,4,5,6,7,8,9,10,11,12, 0,1,2,3,4,5,6,7,8,9,10,11,12};

// ---------------- init: Wigner 3j ----------------
__device__ double d_cg(int l1,int l2,int l3,int m1,int m2,int m3,const double* F){
    if (m1+m2 != m3) return 0.0;
    double pA = (2.0*l3+1.0)*F[l3+l1-l2]*F[l3-l1+l2]*F[l1+l2-l3]/F[l1+l2+l3+1];
    double pB = F[l3+m3]*F[l3-m3]*F[l1-m1]*F[l1+m1]*F[l2-m2]*F[l2+m2];
    double pref = sqrt(pA*pB);
    double s = 0.0;
    for (int k = 0; k <= l1+l2-l3; k++){
        int d0=k, d1=l1+l2-l3-k, d2=l1-m1-k, d3=l2+m2-k, d4=l3-l2+m1+k, d5=l3-l1-m2+k;
        if (d0<0||d1<0||d2<0||d3<0||d4<0||d5<0) continue;
        double den = F[d0]*F[d1]*F[d2]*F[d3]*F[d4]*F[d5];
        s += ((k&1)? -1.0:1.0)/den;
    }
    return pref*s;
}

__device__ void build_q(int l, double2* q){
    int L = 2*l+1;
    for (int i=0;i<L*L;i++) q[i] = make_double2(0.0,0.0);
    double rs2 = 1.0/sqrt(2.0);
    for (int m=-l;m<0;m++){
        q[(l+m)*L + (l-m)] = make_double2(rs2, 0.0);
        q[(l+m)*L + (l+m)] = make_double2(0.0, -rs2);
    }
    q[l*L+l] = make_double2(1.0,0.0);
    for (int m=1;m<=l;m++){
        double sg = (m&1)? -1.0 : 1.0;
        q[(l+m)*L + (l+m)] = make_double2(sg*rs2, 0.0);
        q[(l+m)*L + (l-m)] = make_double2(0.0, sg*rs2);
    }
    double ph = (l % 4 == 0) ? 1.0 : -1.0;
    for (int i=0;i<L*L;i++){ q[i].x *= ph; q[i].y *= ph; }
}

__global__ void k_init_w3j_a(){
    int t = blockIdx.x, chunk = blockIdx.y;
    int l1,l2,l3;
    if (t<6){ l1=c_VAL_L[t][0]; l2=c_VAL_L[t][1]; l3=c_VAL_L[t][2]; }
    else    { l1=c_OUT_L[t-6][0]; l2=c_OUT_L[t-6][1]; l3=c_OUT_L[t-6][2]; }
    int I=2*l1+1, J=2*l2+1, K=2*l3+1;
    int IJK = I*J*K;
    int len = (IJK + WCHUNK - 1)/WCHUNK;
    int lo = chunk*len, hi = min(lo+len, IJK);
    __shared__ double sF[24];
    __shared__ double2 sQ1[169], sQ2[169], sQ3[169];
    __shared__ double sRed[128];
    int tid = threadIdx.x;
    if (tid < 24){ double r=1.0; for (int i=2;i<=tid;i++) r*= (double)i; sF[tid]=r; }
    if (tid==0) build_q(l1,sQ1);
    if (tid==1) build_q(l2,sQ2);
    if (tid==2) build_q(l3,sQ3);
    __syncthreads();
    double ss = 0.0;
    for (int idx=lo+tid; idx<hi; idx+=blockDim.x){
        int j = idx/(J*K); int r = idx - j*J*K; int l = r/K; int n = r - l*K;
        int ia[2] = {j, 2*l1-j};   int ni = (ia[1]==ia[0])?1:2;
        int kb[2] = {l, 2*l2-l};   int nk = (kb[1]==kb[0])?1:2;
        int mc[2] = {n, 2*l3-n};   int nm = (mc[1]==mc[0])?1:2;
        double acc = 0.0;
        for (int a=0;a<ni;a++){
            int i = ia[a];
            double2 q1 = sQ1[i*I+j];
            if (q1.x==0.0 && q1.y==0.0) continue;
            for (int bq=0;bq<nk;bq++){
                int k2 = kb[bq];
                double2 q2 = sQ2[k2*J+l];
                if (q2.x==0.0 && q2.y==0.0) continue;
                double px = q1.x*q2.x - q1.y*q2.y;
                double py = q1.x*q2.y + q1.y*q2.x;
                for (int cq=0;cq<nm;cq++){
                    int m = mc[cq];
                    double2 q3 = sQ3[m*K+n];
                    if (q3.x==0.0 && q3.y==0.0) continue;
                    double cg = d_cg(l1,l2,l3, i-l1, k2-l2, m-l3, sF);
                    if (cg==0.0) continue;
                    acc += (px*q3.x + py*q3.y)*cg;
                }
            }
        }
        g_w3j[t][idx] = (float)acc;
        ss += acc*acc;
    }
    sRed[tid] = ss;
    __syncthreads();
    for (int s=64;s>0;s>>=1){ if (tid<s) sRed[tid]+=sRed[tid+s]; __syncthreads(); }
    if (tid==0) g_psum[t][chunk] = sRed[0];
}

// merged: blocks 0-13 rescale w3j; block 14 computes M
__global__ void k_init_fin(const float* __restrict__ w_lin_in, const float* __restrict__ w_val,
                           const float* __restrict__ w_out, const float* __restrict__ w_lin_out){
    int t = blockIdx.x;
    if (t < 14){
        int l3 = (t<6)? c_VAL_L[t][2] : c_OUT_L[t-6][2];
        int K = 2*l3+1;
        int IJK;
        if (t<6){ int l1=c_VAL_L[t][0], l2=c_VAL_L[t][1]; IJK=(2*l1+1)*(2*l2+1)*K; }
        else    { int l1=c_OUT_L[t-6][0], l2=c_OUT_L[t-6][1]; IJK=(2*l1+1)*(2*l2+1)*K; }
        __shared__ float sScale;
        if (threadIdx.x==0){
            double nrm2 = 0.0;
            for (int c=0;c<WCHUNK;c++) nrm2 += g_psum[t][c];
            double sc = (t<6)? sqrt((double)K/(3.0*CCH)) : sqrt((double)K/(4.0*CCH*CCH));
            sScale = (float)(sc/sqrt(nrm2));
        }
        __syncthreads();
        float s = sScale;
        for (int idx=threadIdx.x; idx<IJK; idx+=blockDim.x)
            g_w3j[t][idx] *= s;
    } else {
        int tid = threadIdx.x;
        if (tid < 24){
            int p = tid/3, qq = tid - p*3;
            int l1o = c_OUT_L[p][0], l2o = c_OUT_L[p][1], l3o = c_OUT_L[p][2];
            const float* wli_p = w_lin_in + (l1o==4 ? 0 : 8);
            const float* wlo   = w_lin_out + (l3o==4 ? 0 : 8);
            int q = (l2o==4 ? 0 : 3) + qq;
            const float* wli_q = w_lin_in + (c_VAL_L[q][0]==4 ? 0 : 8);
            float m = 0.f;
            for (int v=0; v<8; v++){
                float cpv = 0.f;
                for (int u=0; u<8; u++){
                    float wu = wli_p[u];
                    const float* wo = w_out + ((p*8+u)*8+v)*8;
                    for (int w=0; w<8; w++) cpv += wu * wo[w] * wlo[w];
                }
                float aqv = 0.f;
                for (int u=0; u<8; u++) aqv += wli_q[u]*w_val[(q*8+u)*8+v];
                m += cpv*aqv;
            }
            g_M[p][qq] = m * 0.35355339059327373f;
        }
    }
}

// ---------------- prep: per-node bf16 hi/lo features, rv ----------------
__global__ void k_prep(const float* __restrict__ feat, const float* __restrict__ sh_lr,
                       const float* __restrict__ log_s, const float* __restrict__ pos_w,
                       const float* __restrict__ pos_b){
    __shared__ float sW[2670];
    __shared__ float sFt[8][22];
    __shared__ float sY[8][6];
    int tid = threadIdx.x, warp = tid>>5, lane = tid&31;
    for (int p=0;p<6;p++)
        for (int i=tid;i<c_VAL_SZ[p];i+=blockDim.x) sW[c_VAL_OFF[p]+i] = g_w3j[p][i];
    int node = blockIdx.x*8 + warp;
    int b = node >> 12, n = node & (NN-1);
    const float* f = feat + ((size_t)b*NN + n)*22;
    if (lane < 22) sFt[warp][lane] = f[lane];
    if (lane < 6)  sY[warp][lane]  = sh_lr[n*6+lane];
    __syncthreads();
    float n4=0.f, n6=0.f;
    #pragma unroll
    for (int d=0; d<9; d++){ float v=sFt[warp][d]; n4 += v*v; }
    #pragma unroll
    for (int d=9; d<22; d++){ float v=sFt[warp][d]; n6 += v*v; }
    float s4 = __expf(log_s[0]), s6 = __expf(log_s[1]);
    float r4 = sqrtf(s4)/fmaxf(sqrtf(n4), 1e-12f);
    float r6 = sqrtf(s6)/fmaxf(sqrtf(n6), 1e-12f);
    float pb = pos_b[0];
    #pragma unroll
    for (int j=0;j<6;j++) pb += sY[warp][j]*pos_w[j];
    float v;
    if (lane < 9)       v = sFt[warp][lane]*r4;
    else if (lane < 22) v = sFt[warp][lane]*r6;
    else                v = 0.f;
    float vq = (lane==22) ? 1.0f : v;
    float vk = (lane==22) ? pb   : v;
    {
        __nv_bfloat16 hq = __float2bfloat16(vq);
        g_fqh[b][n][lane] = hq;
        g_fql[b][n][lane] = __float2bfloat16(vq - __bfloat162float(hq));
        __nv_bfloat16 hk = __float2bfloat16(vk);
        g_fkh[b][n][lane] = hk;
        g_fkl[b][n][lane] = __float2bfloat16(vk - __bfloat162float(hk));
    }
    float* rv = &g_rv[b][n][0];
    for (int t=lane; t<68; t+=32){
        if (t >= 66){ rv[t] = 0.f; continue; }
        int p = c_T2P[t], k = c_T2K[t];
        int l1 = c_VAL_L[p][0];
        int I = 2*l1+1, J = 2*c_VAL_L[p][1]+1, K = 2*c_VAL_L[p][2]+1;
        int foff = (l1==4)? 0 : 9;
        const float* w = sW + c_VAL_OFF[p];
        float r = 0.f;
        if (J == 1){
            float y0 = sY[warp][0];
            for (int i=0;i<I;i++) r += sFt[warp][foff+i]*y0*w[i*K+k];
        } else {
            for (int i=0;i<I;i++){
                float fi = sFt[warp][foff+i];
                #pragma unroll
                for (int j=0;j<5;j++) r += fi*sY[warp][1+j]*w[(i*5+j)*K+k];
            }
        }
        rv[t] = r;
    }
}

// ---------------- transpose rv -> fp16 rvT[72][NN], row 66 = ones ----------------
__global__ void k_trans(){
    __shared__ float sm[64][68];
    int b = blockIdx.y;
    int n0 = blockIdx.x*64;
    int tid = threadIdx.x;
    for (int i=tid; i<64*17; i+=256){
        int r = i/17, f4 = i%17;
        *(float4*)&sm[r][f4*4] = *(const float4*)&g_rv[b][n0+r][f4*4];
    }
    __syncthreads();
    for (int t=tid; t<72*64; t+=256){
        int d = t/64, nn = t%64;
        float v;
        if (d < 66) v = sm[nn][d];
        else if (d == 66) v = 1.0f;
        else v = 0.0f;
        g_rvTh[b][d][n0+nn] = __float2half(v);
    }
}

// ---------------- fused attention ----------------
// scores: 3-term bf16 MMA (exact to ~2^-17). PV: single-term fp16 MMA.
// 3-stage cp.async K/V pipeline, ONE barrier per chunk. Ones-row denominator.
// SMEM: Qhi[128][40]@0 (10240), Qlo@10240; Khi/Klo stage s @20480+s*10240 (+5120 lo);
//       V fp16 stage s: [72][72] @51200+s*10368.
#define ATT_SMEM 82304

__global__ void __launch_bounds__(256,1) k_attn(){
    extern __shared__ __align__(16) char smem[];
    uint32_t sb = s2u(smem);
    int b = blockIdx.y, qt = blockIdx.x;
    int tid = threadIdx.x, wid = tid>>5, lane = tid&31;
    int m0 = wid*16;

    auto loadQ = [&](){
        #pragma unroll
        for (int j=0;j<4;j++){
            int idx = tid + j*256;
            int plane = idx>>9, rr = idx&511;
            int row = rr>>2, seg = rr&3;
            const __nv_bfloat16* src = plane ? &g_fql[b][qt*128+row][seg*8] : &g_fqh[b][qt*128+row][seg*8];
            cpasync16(sb + plane*10240 + row*80 + seg*16, src);
        }
    };
    auto loadK = [&](int c){
        uint32_t kb2 = sb + 20480 + (uint32_t)(c%3)*10240;
        int kbase = c*64;
        #pragma unroll
        for (int j=0;j<2;j++){
            int idx = tid + j*256;
            int plane = idx>>8, rr = idx&255;
            int row = rr>>2, seg = rr&3;
            const __nv_bfloat16* src = plane ? &g_fkl[b][kbase+row][seg*8] : &g_fkh[b][kbase+row][seg*8];
            cpasync16(kb2 + plane*5120 + row*80 + seg*16, src);
        }
    };
    auto loadV = [&](int c){
        uint32_t vb = sb + 51200 + (uint32_t)(c%3)*10368;
        int kbase = c*64;
        #pragma unroll
        for (int j=0;j<3;j++){
            int idx = tid + j*256;
            if (idx < 576){
                int row = idx>>3, seg = idx&7;
                cpasync16(vb + row*144 + seg*16, &g_rvTh[b][row][kbase+seg*8]);
            }
        }
    };

    loadQ(); loadK(0); loadV(0); CP_COMMIT();
    loadK(1); loadV(1); CP_COMMIT();

    float acc[36];
    #pragma unroll
    for (int i=0;i<36;i++) acc[i]=0.f;

    uint32_t qh[2][4], ql[2][4];
    bool qloaded = false;

    for (int c=0; c<64; c++){
        if (c < 63) asm volatile("cp.async.wait_group 1;" ::: "memory");
        else        asm volatile("cp.async.wait_group 0;" ::: "memory");
        __syncthreads();
        if (c+2 < 64){ loadK(c+2); loadV(c+2); CP_COMMIT(); }

        if (!qloaded){
            uint32_t aQh = sb +          ((m0 + (lane&15))*40 + (lane>>4)*8)*2;
            uint32_t aQl = sb + 10240u + ((m0 + (lane&15))*40 + (lane>>4)*8)*2;
            #pragma unroll
            for (int ks=0; ks<2; ks++){
                ldmx4(qh[ks][0],qh[ks][1],qh[ks][2],qh[ks][3], aQh + ks*32);
                ldmx4(ql[ks][0],ql[ks][1],ql[ks][2],ql[ks][3], aQl + ks*32);
            }
            qloaded = true;
        }

        uint32_t khi = sb + 20480 + (uint32_t)(c%3)*10240;
        uint32_t klo = khi + 5120;
        uint32_t vh  = sb + 51200 + (uint32_t)(c%3)*10368;
        uint32_t b4Off = (((lane&7) + ((lane>>3)&1)*8)*72 + (lane>>4)*8)*2;
        uint32_t b2Off = ((64 + (lane&7))*72 + ((lane>>3)&1)*8)*2;
        uint32_t kRow  = ((lane&7)*40 + ((lane>>3)&1)*8)*2;

        #pragma unroll
        for (int ks2=0; ks2<4; ks2++){
            // --- scores (3-term bf16) ---
            float S[8];
            #pragma unroll
            for (int i=0;i<8;i++) S[i]=0.f;
            #pragma unroll
            for (int half=0; half<2; half++){
                int nt = 2*ks2 + half;
                uint32_t kbase_off = nt*8*40*2;
                #pragma unroll
                for (int ks=0; ks<2; ks++){
                    uint32_t bh0,bh1, bl0,bl1;
                    ldmx2(bh0,bh1, khi + kbase_off + kRow + ks*32);
                    mma16816(S+half*4, qh[ks][0],qh[ks][1],qh[ks][2],qh[ks][3], bh0, bh1);
                    mma16816(S+half*4, ql[ks][0],ql[ks][1],ql[ks][2],ql[ks][3], bh0, bh1);
                    ldmx2(bl0,bl1, klo + kbase_off + kRow + ks*32);
                    mma16816(S+half*4, qh[ks][0],qh[ks][1],qh[ks][2],qh[ks][3], bl0, bl1);
                }
            }
            // --- exp + fp16 A-frag ---
            float p[8];
            #pragma unroll
            for (int i=0;i<8;i++) p[i] = __expf(S[i]);
            uint32_t ah[4];
            ah[0] = cvtpackh(p[1], p[0]);
            ah[1] = cvtpackh(p[3], p[2]);
            ah[2] = cvtpackh(p[5], p[4]);
            ah[3] = cvtpackh(p[7], p[6]);
            // --- P @ V (single-term fp16) ---
            uint32_t kofs = ks2*32;
            #pragma unroll
            for (int g=0; g<4; g++){
                uint32_t r0,r1,r2,r3;
                ldmx4(r0,r1,r2,r3, vh + b4Off + g*(16*72*2) + kofs);
                mma16816h(acc + (2*g)*4,   ah[0],ah[1],ah[2],ah[3], r0, r2);
                mma16816h(acc + (2*g+1)*4, ah[0],ah[1],ah[2],ah[3], r1, r3);
            }
            {
                uint32_t r0,r1;
                ldmx2(r0,r1, vh + b2Off + kofs);
                mma16816h(acc + 32, ah[0],ah[1],ah[2],ah[3], r0, r1);
            }
        }
    }

    // epilogue: col 66 = row sum
    const unsigned FULL = 0xffffffffu;
    float s_hi = __shfl_sync(FULL, acc[32], (lane & 0x1c) + 1);
    float s_lo = __shfl_sync(FULL, acc[34], (lane & 0x1c) + 1);
    float inv_hi = 1.0f/s_hi, inv_lo = 1.0f/s_lo;
    int r0 = qt*128 + m0 + (lane>>2);
    int r1 = r0 + 8;
    int colb = 2*(lane&3);
    #pragma unroll
    for (int nt=0; nt<9; nt++){
        int j = nt*8 + colb;
        if (j < 66){
            float v0 = acc[nt*4+0]*inv_hi, v1 = acc[nt*4+1]*inv_hi;
            ull pk; asm("mov.b64 %0, {%1,%2};" : "=l"(pk) : "f"(v0), "f"(v1));
            *(ull*)&g_ctx[b][r0][j] = pk;
            float w0 = acc[nt*4+2]*inv_lo, w1 = acc[nt*4+3]*inv_lo;
            ull pk2; asm("mov.b64 %0, {%1,%2};" : "=l"(pk2) : "f"(w0), "f"(w1));
            *(ull*)&g_ctx[b][r1][j] = pk2;
        }
    }
}

// ---------------- out ----------------
template<int I,int J,int K>
__device__ __forceinline__ float path_term(const float* fp, const float* c0, const float* c1, const float* c2,
                                           float m0, float m1, float m2, const float* w, int k){
    float e[J];
    #pragma unroll
    for (int j=0;j<J;j++) e[j] = m0*c0[j] + m1*c1[j] + m2*c2[j];
    float d = 0.f;
    for (int i=0;i<I;i++){
        float fi = fp[i];
        #pragma unroll
        for (int j=0;j<J;j++) d += fi*e[j]*w[(i*J+j)*K+k];
    }
    return d;
}

__global__ void k_out(const float* __restrict__ feat, float* __restrict__ out){
    __shared__ float sW[10648];
    __shared__ float sFt[8][22];
    __shared__ float sC[8][66];
    int tid = threadIdx.x, warp = tid>>5, lane = tid&31;
    for (int p=0;p<8;p++)
        for (int i=tid;i<c_OUT_SZ[p];i+=blockDim.x) sW[c_OUT_OFF[p]+i] = g_w3j[6+p][i];
    int node = blockIdx.x*8 + warp;
    int b = node >> 12, n = node & (NN-1);
    if (lane < 22) sFt[warp][lane] = feat[((size_t)b*NN+n)*22 + lane];
    for (int t=lane; t<66; t+=32) sC[warp][t] = g_ctx[b][n][t];
    __syncthreads();
    if (lane < 22){
        const float* F = sFt[warp];
        const float* C = sC[warp];
        float d;
        if (lane < 9){
            int k = lane;
            d  = path_term<9 ,9 ,9>(F  , C   , C+9 , C+18, g_M[0][0],g_M[0][1],g_M[0][2], sW+c_OUT_OFF[0], k);
            d += path_term<9 ,13,9>(F  , C+27, C+40, C+53, g_M[1][0],g_M[1][1],g_M[1][2], sW+c_OUT_OFF[1], k);
            d += path_term<13,9 ,9>(F+9, C   , C+9 , C+18, g_M[2][0],g_M[2][1],g_M[2][2], sW+c_OUT_OFF[2], k);
            d += path_term<13,13,9>(F+9, C+27, C+40, C+53, g_M[3][0],g_M[3][1],g_M[3][2], sW+c_OUT_OFF[3], k);
        } else {
            int k = lane - 9;
            d  = path_term<9 ,9 ,13>(F  , C   , C+9 , C+18, g_M[4][0],g_M[4][1],g_M[4][2], sW+c_OUT_OFF[4], k);
            d += path_term<9 ,13,13>(F  , C+27, C+40, C+53, g_M[5][0],g_M[5][1],g_M[5][2], sW+c_OUT_OFF[5], k);
            d += path_term<13,9 ,13>(F+9, C   , C+9 , C+18, g_M[6][0],g_M[6][1],g_M[6][2], sW+c_OUT_OFF[6], k);
            d += path_term<13,13,13>(F+9, C+27, C+40, C+53, g_M[7][0],g_M[7][1],g_M[7][2], sW+c_OUT_OFF[7], k);
        }
        out[((size_t)b*NN+n)*22 + lane] = d;
    }
}

// ---------------- launch ----------------
extern "C" void kernel_launch(void* const* d_in, const int* in_sizes, int n_in,
                              void* d_out, int out_size){
    const float* feat      = (const float*)d_in[0];
    const float* sh_lr     = (const float*)d_in[1];
    const float* log_s     = (const float*)d_in[2];
    const float* pos_w     = (const float*)d_in[3];
    const float* pos_b     = (const float*)d_in[4];
    const float* w_lin_in  = (const float*)d_in[5];
    const float* w_val     = (const float*)d_in[6];
    const float* w_out     = (const float*)d_in[7];
    const float* w_lin_out = (const float*)d_in[8];
    float* out = (float*)d_out;

    cudaFuncSetAttribute(k_attn, cudaFuncAttributeMaxDynamicSharedMemorySize, ATT_SMEM);

    dim3 gi(14, WCHUNK);
    k_init_w3j_a<<<gi, 128>>>();
    k_init_fin<<<15, 128>>>(w_lin_in, w_val, w_out, w_lin_out);
    k_prep<<<(NB*NN)/8, 256>>>(feat, sh_lr, log_s, pos_w, pos_b);
    k_trans<<<dim3(NN/64, NB), 256>>>();
    k_attn<<<dim3(NN/128, NB), 256, ATT_SMEM>>>();
    k_out<<<(NB*NN)/8, 256>>>(feat, out);
}

// round 12
// speedup vs baseline: 1.5782x; 1.5782x over previous
#include <cuda_runtime.h>
#include <cuda_bf16.h>
#include <cuda_fp16.h>
#include <math.h>
#include <stdint.h>

#define NB 4
#define NN 4096
#define CCH 8
#define WCHUNK 64

typedef unsigned long long ull;

__device__ __forceinline__ uint32_t s2u(const void* p){
    uint32_t a;
    asm("{ .reg .u64 t; cvta.to.shared.u64 t, %1; cvt.u32.u64 %0, t; }" : "=r"(a) : "l"(p));
    return a;
}
__device__ __forceinline__ void cpasync16(uint32_t dst, const void* src){
    asm volatile("cp.async.cg.shared.global [%0], [%1], 16;" :: "r"(dst), "l"(src));
}
#define CP_COMMIT() asm volatile("cp.async.commit_group;" ::: "memory")

__device__ __forceinline__ void ldmx4(uint32_t& r0, uint32_t& r1, uint32_t& r2, uint32_t& r3, uint32_t a){
    asm volatile("ldmatrix.sync.aligned.m8n8.x4.shared.b16 {%0,%1,%2,%3}, [%4];"
        : "=r"(r0), "=r"(r1), "=r"(r2), "=r"(r3) : "r"(a));
}
__device__ __forceinline__ void ldmx2(uint32_t& r0, uint32_t& r1, uint32_t a){
    asm volatile("ldmatrix.sync.aligned.m8n8.x2.shared.b16 {%0,%1}, [%2];"
        : "=r"(r0), "=r"(r1) : "r"(a));
}
__device__ __forceinline__ void mma16816(float* d, uint32_t a0, uint32_t a1, uint32_t a2, uint32_t a3,
                                         uint32_t b0, uint32_t b1){
    asm volatile("mma.sync.aligned.m16n8k16.row.col.f32.bf16.bf16.f32 "
        "{%0,%1,%2,%3}, {%4,%5,%6,%7}, {%8,%9}, {%0,%1,%2,%3};"
        : "+f"(d[0]), "+f"(d[1]), "+f"(d[2]), "+f"(d[3])
        : "r"(a0), "r"(a1), "r"(a2), "r"(a3), "r"(b0), "r"(b1));
}
__device__ __forceinline__ void mma16816h(float* d, uint32_t a0, uint32_t a1, uint32_t a2, uint32_t a3,
                                          uint32_t b0, uint32_t b1){
    asm volatile("mma.sync.aligned.m16n8k16.row.col.f32.f16.f16.f32 "
        "{%0,%1,%2,%3}, {%4,%5,%6,%7}, {%8,%9}, {%0,%1,%2,%3};"
        : "+f"(d[0]), "+f"(d[1]), "+f"(d[2]), "+f"(d[3])
        : "r"(a0), "r"(a1), "r"(a2), "r"(a3), "r"(b0), "r"(b1));
}
__device__ __forceinline__ uint32_t cvtpackh(float hi, float lo){
    uint32_t r; asm("cvt.rn.f16x2.f32 %0, %1, %2;" : "=r"(r) : "f"(hi), "f"(lo)); return r;
}

// ---------------- device global scratch ----------------
__device__ float g_w3j[14][2197];
__device__ double g_psum[14][WCHUNK];
__device__ float g_M[8][3];
__device__ float g_rv[NB][NN][68];                 // 66 used
__device__ float g_ctx[NB][NN][68];                // 66 used
__device__ __nv_bfloat16 g_fqh[NB][NN][32];        // query feats hi (22 + feat22=1)
__device__ __nv_bfloat16 g_fql[NB][NN][32];        // query feats lo
__device__ __nv_bfloat16 g_fkh[NB][NN][32];        // key feats hi (22 + feat22=pb)
__device__ __nv_bfloat16 g_fkl[NB][NN][32];        // key feats lo
__device__ __half g_rvTh[NB][72][NN];              // transposed V fp16, row 66 = ones

__constant__ int c_VAL_L[6][3] = {{4,0,4},{4,2,4},{6,2,4},{4,2,6},{6,0,6},{6,2,6}};
__constant__ int c_OUT_L[8][3] = {{4,4,4},{4,6,4},{6,4,4},{6,6,4},{4,4,6},{4,6,6},{6,4,6},{6,6,6}};
__constant__ int c_OUT_OFF[8] = {0,729,1782,2835,4356,5409,6930,8451};
__constant__ int c_VAL_OFF[6] = {0,81,486,1071,1656,1825};
__constant__ int c_VAL_SZ[6]  = {81,405,585,585,169,845};
__constant__ int c_OUT_SZ[8]  = {729,1053,1053,1521,1053,1521,1521,2197};

// ---------------- init: Wigner 3j ----------------
__device__ double d_cg(int l1,int l2,int l3,int m1,int m2,int m3,const double* F){
    if (m1+m2 != m3) return 0.0;
    double pA = (2.0*l3+1.0)*F[l3+l1-l2]*F[l3-l1+l2]*F[l1+l2-l3]/F[l1+l2+l3+1];
    double pB = F[l3+m3]*F[l3-m3]*F[l1-m1]*F[l1+m1]*F[l2-m2]*F[l2+m2];
    double pref = sqrt(pA*pB);
    double s = 0.0;
    for (int k = 0; k <= l1+l2-l3; k++){
        int d0=k, d1=l1+l2-l3-k, d2=l1-m1-k, d3=l2+m2-k, d4=l3-l2+m1+k, d5=l3-l1-m2+k;
        if (d0<0||d1<0||d2<0||d3<0||d4<0||d5<0) continue;
        double den = F[d0]*F[d1]*F[d2]*F[d3]*F[d4]*F[d5];
        s += ((k&1)? -1.0:1.0)/den;
    }
    return pref*s;
}

__device__ void build_q(int l, double2* q){
    int L = 2*l+1;
    for (int i=0;i<L*L;i++) q[i] = make_double2(0.0,0.0);
    double rs2 = 1.0/sqrt(2.0);
    for (int m=-l;m<0;m++){
        q[(l+m)*L + (l-m)] = make_double2(rs2, 0.0);
        q[(l+m)*L + (l+m)] = make_double2(0.0, -rs2);
    }
    q[l*L+l] = make_double2(1.0,0.0);
    for (int m=1;m<=l;m++){
        double sg = (m&1)? -1.0 : 1.0;
        q[(l+m)*L + (l+m)] = make_double2(sg*rs2, 0.0);
        q[(l+m)*L + (l-m)] = make_double2(0.0, sg*rs2);
    }
    double ph = (l % 4 == 0) ? 1.0 : -1.0;
    for (int i=0;i<L*L;i++){ q[i].x *= ph; q[i].y *= ph; }
}

__global__ void k_init_w3j_a(){
    int t = blockIdx.x, chunk = blockIdx.y;
    int l1,l2,l3;
    if (t<6){ l1=c_VAL_L[t][0]; l2=c_VAL_L[t][1]; l3=c_VAL_L[t][2]; }
    else    { l1=c_OUT_L[t-6][0]; l2=c_OUT_L[t-6][1]; l3=c_OUT_L[t-6][2]; }
    int I=2*l1+1, J=2*l2+1, K=2*l3+1;
    int IJK = I*J*K;
    int len = (IJK + WCHUNK - 1)/WCHUNK;
    int lo = chunk*len, hi = min(lo+len, IJK);
    __shared__ double sF[24];
    __shared__ double2 sQ1[169], sQ2[169], sQ3[169];
    __shared__ double sRed[128];
    int tid = threadIdx.x;
    if (tid < 24){ double r=1.0; for (int i=2;i<=tid;i++) r*= (double)i; sF[tid]=r; }
    if (tid==0) build_q(l1,sQ1);
    if (tid==1) build_q(l2,sQ2);
    if (tid==2) build_q(l3,sQ3);
    __syncthreads();
    double ss = 0.0;
    for (int idx=lo+tid; idx<hi; idx+=blockDim.x){
        int j = idx/(J*K); int r = idx - j*J*K; int l = r/K; int n = r - l*K;
        int ia[2] = {j, 2*l1-j};   int ni = (ia[1]==ia[0])?1:2;
        int kb[2] = {l, 2*l2-l};   int nk = (kb[1]==kb[0])?1:2;
        int mc[2] = {n, 2*l3-n};   int nm = (mc[1]==mc[0])?1:2;
        double acc = 0.0;
        for (int a=0;a<ni;a++){
            int i = ia[a];
            double2 q1 = sQ1[i*I+j];
            if (q1.x==0.0 && q1.y==0.0) continue;
            for (int bq=0;bq<nk;bq++){
                int k2 = kb[bq];
                double2 q2 = sQ2[k2*J+l];
                if (q2.x==0.0 && q2.y==0.0) continue;
                double px = q1.x*q2.x - q1.y*q2.y;
                double py = q1.x*q2.y + q1.y*q2.x;
                for (int cq=0;cq<nm;cq++){
                    int m = mc[cq];
                    double2 q3 = sQ3[m*K+n];
                    if (q3.x==0.0 && q3.y==0.0) continue;
                    double cg = d_cg(l1,l2,l3, i-l1, k2-l2, m-l3, sF);
                    if (cg==0.0) continue;
                    acc += (px*q3.x + py*q3.y)*cg;
                }
            }
        }
        g_w3j[t][idx] = (float)acc;
        ss += acc*acc;
    }
    sRed[tid] = ss;
    __syncthreads();
    for (int s=64;s>0;s>>=1){ if (tid<s) sRed[tid]+=sRed[tid+s]; __syncthreads(); }
    if (tid==0) g_psum[t][chunk] = sRed[0];
}

__global__ void k_init_w3j_b(){
    int t = blockIdx.x;
    int l3 = (t<6)? c_VAL_L[t][2] : c_OUT_L[t-6][2];
    int K = 2*l3+1;
    int IJK;
    if (t<6){ int l1=c_VAL_L[t][0], l2=c_VAL_L[t][1]; IJK=(2*l1+1)*(2*l2+1)*K; }
    else    { int l1=c_OUT_L[t-6][0], l2=c_OUT_L[t-6][1]; IJK=(2*l1+1)*(2*l2+1)*K; }
    __shared__ float sScale;
    if (threadIdx.x==0){
        double nrm2 = 0.0;
        for (int c=0;c<WCHUNK;c++) nrm2 += g_psum[t][c];
        double sc = (t<6)? sqrt((double)K/(3.0*CCH)) : sqrt((double)K/(4.0*CCH*CCH));
        sScale = (float)(sc/sqrt(nrm2));
    }
    __syncthreads();
    float s = sScale;
    for (int idx=threadIdx.x; idx<IJK; idx+=blockDim.x)
        g_w3j[t][idx] *= s;
}

// ---------------- init: M[p][qq] ----------------
__global__ void k_init_small(const float* __restrict__ w_lin_in, const float* __restrict__ w_val,
                             const float* __restrict__ w_out, const float* __restrict__ w_lin_out){
    int tid = threadIdx.x;
    if (tid < 24){
        int p = tid/3, qq = tid - p*3;
        int l1o = c_OUT_L[p][0], l2o = c_OUT_L[p][1], l3o = c_OUT_L[p][2];
        const float* wli_p = w_lin_in + (l1o==4 ? 0 : 8);
        const float* wlo   = w_lin_out + (l3o==4 ? 0 : 8);
        int q = (l2o==4 ? 0 : 3) + qq;
        const float* wli_q = w_lin_in + (c_VAL_L[q][0]==4 ? 0 : 8);
        float m = 0.f;
        for (int v=0; v<8; v++){
            float cpv = 0.f;
            for (int u=0; u<8; u++){
                float wu = wli_p[u];
                const float* wo = w_out + ((p*8+u)*8+v)*8;
                for (int w=0; w<8; w++) cpv += wu * wo[w] * wlo[w];
            }
            float aqv = 0.f;
            for (int u=0; u<8; u++) aqv += wli_q[u]*w_val[(q*8+u)*8+v];
            m += cpv*aqv;
        }
        g_M[p][qq] = m * 0.35355339059327373f;
    }
}

// ---------------- prep: per-node bf16 hi/lo features, rv ----------------
__global__ void k_prep(const float* __restrict__ feat, const float* __restrict__ sh_lr,
                       const float* __restrict__ log_s, const float* __restrict__ pos_w,
                       const float* __restrict__ pos_b){
    __shared__ float sW[2670];
    __shared__ float sFt[8][22];
    __shared__ float sY[8][6];
    int tid = threadIdx.x, warp = tid>>5, lane = tid&31;
    for (int p=0;p<6;p++)
        for (int i=tid;i<c_VAL_SZ[p];i+=blockDim.x) sW[c_VAL_OFF[p]+i] = g_w3j[p][i];
    int node = blockIdx.x*8 + warp;
    int b = node >> 12, n = node & (NN-1);
    const float* f = feat + ((size_t)b*NN + n)*22;
    if (lane < 22) sFt[warp][lane] = f[lane];
    if (lane < 6)  sY[warp][lane]  = sh_lr[n*6+lane];
    __syncthreads();
    float n4=0.f, n6=0.f;
    #pragma unroll
    for (int d=0; d<9; d++){ float v=sFt[warp][d]; n4 += v*v; }
    #pragma unroll
    for (int d=9; d<22; d++){ float v=sFt[warp][d]; n6 += v*v; }
    float s4 = __expf(log_s[0]), s6 = __expf(log_s[1]);
    float r4 = sqrtf(s4)/fmaxf(sqrtf(n4), 1e-12f);
    float r6 = sqrtf(s6)/fmaxf(sqrtf(n6), 1e-12f);
    float pb = pos_b[0];
    #pragma unroll
    for (int j=0;j<6;j++) pb += sY[warp][j]*pos_w[j];
    float v;
    if (lane < 9)       v = sFt[warp][lane]*r4;
    else if (lane < 22) v = sFt[warp][lane]*r6;
    else                v = 0.f;
    float vq = (lane==22) ? 1.0f : v;
    float vk = (lane==22) ? pb   : v;
    {
        __nv_bfloat16 hq = __float2bfloat16(vq);
        g_fqh[b][n][lane] = hq;
        g_fql[b][n][lane] = __float2bfloat16(vq - __bfloat162float(hq));
        __nv_bfloat16 hk = __float2bfloat16(vk);
        g_fkh[b][n][lane] = hk;
        g_fkl[b][n][lane] = __float2bfloat16(vk - __bfloat162float(hk));
    }
    float* rv = &g_rv[b][n][0];
    for (int t=lane; t<68; t+=32){
        if (t >= 66){ rv[t] = 0.f; continue; }
        int p,k;
        if (t < 27){ p = t/9; k = t - p*9; } else { int u=t-27; p = 3 + u/13; k = u - (p-3)*13; }
        int l1 = c_VAL_L[p][0], l2 = c_VAL_L[p][1];
        int I = 2*l1+1, J = 2*l2+1, K = 2*c_VAL_L[p][2]+1;
        int foff = (l1==4)? 0 : 9;
        const float* w = sW + c_VAL_OFF[p];
        float r = 0.f;
        if (J == 1){
            float y0 = sY[warp][0];
            for (int i=0;i<I;i++) r += sFt[warp][foff+i]*y0*w[i*K+k];
        } else {
            for (int i=0;i<I;i++){
                float fi = sFt[warp][foff+i];
                #pragma unroll
                for (int j=0;j<5;j++) r += fi*sY[warp][1+j]*w[(i*5+j)*K+k];
            }
        }
        rv[t] = r;
    }
}

// ---------------- transpose rv -> fp16 rvT[72][NN], row 66 = ones ----------------
__global__ void k_trans(){
    __shared__ float sm[64][68];
    int b = blockIdx.y;
    int n0 = blockIdx.x*64;
    int tid = threadIdx.x;
    for (int i=tid; i<64*17; i+=256){
        int r = i/17, f4 = i%17;
        *(float4*)&sm[r][f4*4] = *(const float4*)&g_rv[b][n0+r][f4*4];
    }
    __syncthreads();
    for (int t=tid; t<72*64; t+=256){
        int d = t/64, nn = t%64;
        float v;
        if (d < 66) v = sm[nn][d];
        else if (d == 66) v = 1.0f;
        else v = 0.0f;
        g_rvTh[b][d][n0+nn] = __float2half(v);
    }
}

// ---------------- fused attention (R8 structure; PV = single-term fp16) ----------------
// SMEM layout (bytes from base):
//   Qhi [128][40]  @ 0       (10240)
//   Qlo [128][40]  @ 10240   (10240)
//   K stage s: Khi [64][40] @ 20480+s*10240, Klo @ +5120
//   V stage s (fp16): [72][72] @ 40960+s*10368
#define ATT_SMEM 61696

__global__ void __launch_bounds__(256,1) k_attn(){
    extern __shared__ __align__(16) char smem[];
    uint32_t sb = s2u(smem);
    int b = blockIdx.y, qt = blockIdx.x;
    int tid = threadIdx.x, wid = tid>>5, lane = tid&31;
    int m0 = wid*16;

    auto loadQ = [&](){
        #pragma unroll
        for (int j=0;j<4;j++){
            int idx = tid + j*256;        // 1024 = 2 planes * 128 rows * 4 segs
            int plane = idx>>9, rr = idx&511;
            int row = rr>>2, seg = rr&3;
            const __nv_bfloat16* src = plane ? &g_fql[b][qt*128+row][seg*8] : &g_fqh[b][qt*128+row][seg*8];
            cpasync16(sb + plane*10240 + row*80 + seg*16, src);
        }
    };
    auto loadK = [&](int c){
        uint32_t kb2 = sb + 20480 + (c&1)*10240;
        int kbase = c*64;
        #pragma unroll
        for (int j=0;j<2;j++){
            int idx = tid + j*256;        // 512 = 2 planes * 64 rows * 4 segs
            int plane = idx>>8, rr = idx&255;
            int row = rr>>2, seg = rr&3;
            const __nv_bfloat16* src = plane ? &g_fkl[b][kbase+row][seg*8] : &g_fkh[b][kbase+row][seg*8];
            cpasync16(kb2 + plane*5120 + row*80 + seg*16, src);
        }
    };
    auto loadV = [&](int c){
        uint32_t vb = sb + 40960 + (c&1)*10368;
        int kbase = c*64;
        #pragma unroll
        for (int j=0;j<3;j++){
            int idx = tid + j*256;        // 576 = 72 rows * 8 segs
            if (idx < 576){
                int row = idx>>3, seg = idx&7;
                cpasync16(vb + row*144 + seg*16, &g_rvTh[b][row][kbase+seg*8]);
            }
        }
    };

    loadQ(); loadK(0); loadV(0); CP_COMMIT();

    float acc[36];
    #pragma unroll
    for (int i=0;i<36;i++) acc[i]=0.f;

    uint32_t qh[2][4], ql[2][4];
    bool qloaded = false;

    for (int c=0; c<64; c++){
        if (c+1 < 64){ loadK(c+1); loadV(c+1); CP_COMMIT(); }
        if (c+1 < 64) asm volatile("cp.async.wait_group 1;" ::: "memory");
        else          asm volatile("cp.async.wait_group 0;" ::: "memory");
        __syncthreads();

        if (!qloaded){
            uint32_t aQh = sb +          ((m0 + (lane&15))*40 + (lane>>4)*8)*2;
            uint32_t aQl = sb + 10240u + ((m0 + (lane&15))*40 + (lane>>4)*8)*2;
            #pragma unroll
            for (int ks=0; ks<2; ks++){
                ldmx4(qh[ks][0],qh[ks][1],qh[ks][2],qh[ks][3], aQh + ks*32);
                ldmx4(ql[ks][0],ql[ks][1],ql[ks][2],ql[ks][3], aQl + ks*32);
            }
            qloaded = true;
        }

        uint32_t khi = sb + 20480 + (c&1)*10240;
        uint32_t klo = khi + 5120;
        uint32_t vh  = sb + 40960 + (c&1)*10368;
        uint32_t b4Off = (((lane&7) + ((lane>>3)&1)*8)*72 + (lane>>4)*8)*2;
        uint32_t b2Off = ((64 + (lane&7))*72 + ((lane>>3)&1)*8)*2;
        uint32_t kRow  = ((lane&7)*40 + ((lane>>3)&1)*8)*2;

        #pragma unroll
        for (int ks2=0; ks2<4; ks2++){
            // --- scores (3-term bf16, exact to ~2^-17) ---
            float S[8];
            #pragma unroll
            for (int i=0;i<8;i++) S[i]=0.f;
            #pragma unroll
            for (int half=0; half<2; half++){
                int nt = 2*ks2 + half;
                uint32_t kbase_off = nt*8*40*2;
                #pragma unroll
                for (int ks=0; ks<2; ks++){
                    uint32_t bh0,bh1, bl0,bl1;
                    ldmx2(bh0,bh1, khi + kbase_off + kRow + ks*32);
                    mma16816(S+half*4, qh[ks][0],qh[ks][1],qh[ks][2],qh[ks][3], bh0, bh1);
                    mma16816(S+half*4, ql[ks][0],ql[ks][1],ql[ks][2],ql[ks][3], bh0, bh1);
                    ldmx2(bl0,bl1, klo + kbase_off + kRow + ks*32);
                    mma16816(S+half*4, qh[ks][0],qh[ks][1],qh[ks][2],qh[ks][3], bl0, bl1);
                }
            }
            // --- exp + fp16 A-frag ---
            float p[8];
            #pragma unroll
            for (int i=0;i<8;i++) p[i] = __expf(S[i]);
            uint32_t ah[4];
            ah[0] = cvtpackh(p[1], p[0]);
            ah[1] = cvtpackh(p[3], p[2]);
            ah[2] = cvtpackh(p[5], p[4]);
            ah[3] = cvtpackh(p[7], p[6]);
            // --- P @ V (single-term fp16) ---
            uint32_t kofs = ks2*32;
            #pragma unroll
            for (int g=0; g<4; g++){
                uint32_t r0,r1,r2,r3;
                ldmx4(r0,r1,r2,r3, vh + b4Off + g*(16*72*2) + kofs);
                mma16816h(acc + (2*g)*4,   ah[0],ah[1],ah[2],ah[3], r0, r2);
                mma16816h(acc + (2*g+1)*4, ah[0],ah[1],ah[2],ah[3], r1, r3);
            }
            {
                uint32_t r0,r1;
                ldmx2(r0,r1, vh + b2Off + kofs);
                mma16816h(acc + 32, ah[0],ah[1],ah[2],ah[3], r0, r1);
            }
        }
        __syncthreads();
    }

    // epilogue: col 66 = row sum
    const unsigned FULL = 0xffffffffu;
    float s_hi = __shfl_sync(FULL, acc[32], (lane & 0x1c) + 1);
    float s_lo = __shfl_sync(FULL, acc[34], (lane & 0x1c) + 1);
    float inv_hi = 1.0f/s_hi, inv_lo = 1.0f/s_lo;
    int r0 = qt*128 + m0 + (lane>>2);
    int r1 = r0 + 8;
    int colb = 2*(lane&3);
    #pragma unroll
    for (int nt=0; nt<9; nt++){
        int j = nt*8 + colb;
        if (j < 66){
            float v0 = acc[nt*4+0]*inv_hi, v1 = acc[nt*4+1]*inv_hi;
            ull pk; asm("mov.b64 %0, {%1,%2};" : "=l"(pk) : "f"(v0), "f"(v1));
            *(ull*)&g_ctx[b][r0][j] = pk;
            float w0 = acc[nt*4+2]*inv_lo, w1 = acc[nt*4+3]*inv_lo;
            ull pk2; asm("mov.b64 %0, {%1,%2};" : "=l"(pk2) : "f"(w0), "f"(w1));
            *(ull*)&g_ctx[b][r1][j] = pk2;
        }
    }
}

// ---------------- out ----------------
template<int I,int J,int K>
__device__ __forceinline__ float path_term(const float* fp, const float* c0, const float* c1, const float* c2,
                                           float m0, float m1, float m2, const float* w, int k){
    float e[J];
    #pragma unroll
    for (int j=0;j<J;j++) e[j] = m0*c0[j] + m1*c1[j] + m2*c2[j];
    float d = 0.f;
    for (int i=0;i<I;i++){
        float fi = fp[i];
        #pragma unroll
        for (int j=0;j<J;j++) d += fi*e[j]*w[(i*J+j)*K+k];
    }
    return d;
}

__global__ void k_out(const float* __restrict__ feat, float* __restrict__ out){
    __shared__ float sW[10648];
    __shared__ float sFt[8][22];
    __shared__ float sC[8][66];
    int tid = threadIdx.x, warp = tid>>5, lane = tid&31;
    for (int p=0;p<8;p++)
        for (int i=tid;i<c_OUT_SZ[p];i+=blockDim.x) sW[c_OUT_OFF[p]+i] = g_w3j[6+p][i];
    int node = blockIdx.x*8 + warp;
    int b = node >> 12, n = node & (NN-1);
    if (lane < 22) sFt[warp][lane] = feat[((size_t)b*NN+n)*22 + lane];
    for (int t=lane; t<66; t+=32) sC[warp][t] = g_ctx[b][n][t];
    __syncthreads();
    if (lane < 22){
        const float* F = sFt[warp];
        const float* C = sC[warp];
        float d;
        if (lane < 9){
            int k = lane;
            d  = path_term<9 ,9 ,9>(F  , C   , C+9 , C+18, g_M[0][0],g_M[0][1],g_M[0][2], sW+c_OUT_OFF[0], k);
            d += path_term<9 ,13,9>(F  , C+27, C+40, C+53, g_M[1][0],g_M[1][1],g_M[1][2], sW+c_OUT_OFF[1], k);
            d += path_term<13,9 ,9>(F+9, C   , C+9 , C+18, g_M[2][0],g_M[2][1],g_M[2][2], sW+c_OUT_OFF[2], k);
            d += path_term<13,13,9>(F+9, C+27, C+40, C+53, g_M[3][0],g_M[3][1],g_M[3][2], sW+c_OUT_OFF[3], k);
        } else {
            int k = lane - 9;
            d  = path_term<9 ,9 ,13>(F  , C   , C+9 , C+18, g_M[4][0],g_M[4][1],g_M[4][2], sW+c_OUT_OFF[4], k);
            d += path_term<9 ,13,13>(F  , C+27, C+40, C+53, g_M[5][0],g_M[5][1],g_M[5][2], sW+c_OUT_OFF[5], k);
            d += path_term<13,9 ,13>(F+9, C   , C+9 , C+18, g_M[6][0],g_M[6][1],g_M[6][2], sW+c_OUT_OFF[6], k);
            d += path_term<13,13,13>(F+9, C+27, C+40, C+53, g_M[7][0],g_M[7][1],g_M[7][2], sW+c_OUT_OFF[7], k);
        }
        out[((size_t)b*NN+n)*22 + lane] = d;
    }
}

// ---------------- launch ----------------
extern "C" void kernel_launch(void* const* d_in, const int* in_sizes, int n_in,
                              void* d_out, int out_size){
    const float* feat      = (const float*)d_in[0];
    const float* sh_lr     = (const float*)d_in[1];
    const float* log_s     = (const float*)d_in[2];
    const float* pos_w     = (const float*)d_in[3];
    const float* pos_b     = (const float*)d_in[4];
    const float* w_lin_in  = (const float*)d_in[5];
    const float* w_val     = (const float*)d_in[6];
    const float* w_out     = (const float*)d_in[7];
    const float* w_lin_out = (const float*)d_in[8];
    float* out = (float*)d_out;

    cudaFuncSetAttribute(k_attn, cudaFuncAttributeMaxDynamicSharedMemorySize, ATT_SMEM);

    dim3 gi(14, WCHUNK);
    k_init_w3j_a<<<gi, 128>>>();
    k_init_w3j_b<<<14, 128>>>();
    k_init_small<<<1,32>>>(w_lin_in, w_val, w_out, w_lin_out);
    k_prep<<<(NB*NN)/8, 256>>>(feat, sh_lr, log_s, pos_w, pos_b);
    k_trans<<<dim3(NN/64, NB), 256>>>();
    k_attn<<<dim3(NN/128, NB), 256, ATT_SMEM>>>();
    k_out<<<(NB*NN)/8, 256>>>(feat, out);
}

// round 13
// speedup vs baseline: 1.5789x; 1.0005x over previous
#include <cuda_runtime.h>
#include <cuda_bf16.h>
#include <cuda_fp16.h>
#include <math.h>
#include <stdint.h>

#define NB 4
#define NN 4096
#define CCH 8
#define WCHUNK 64

typedef unsigned long long ull;

__device__ __forceinline__ uint32_t s2u(const void* p){
    uint32_t a;
    asm("{ .reg .u64 t; cvta.to.shared.u64 t, %1; cvt.u32.u64 %0, t; }" : "=r"(a) : "l"(p));
    return a;
}
__device__ __forceinline__ void cpasync16(uint32_t dst, const void* src){
    asm volatile("cp.async.cg.shared.global [%0], [%1], 16;" :: "r"(dst), "l"(src));
}
#define CP_COMMIT() asm volatile("cp.async.commit_group;" ::: "memory")

__device__ __forceinline__ void ldmx4(uint32_t& r0, uint32_t& r1, uint32_t& r2, uint32_t& r3, uint32_t a){
    asm volatile("ldmatrix.sync.aligned.m8n8.x4.shared.b16 {%0,%1,%2,%3}, [%4];"
        : "=r"(r0), "=r"(r1), "=r"(r2), "=r"(r3) : "r"(a));
}
__device__ __forceinline__ void ldmx2(uint32_t& r0, uint32_t& r1, uint32_t a){
    asm volatile("ldmatrix.sync.aligned.m8n8.x2.shared.b16 {%0,%1}, [%2];"
        : "=r"(r0), "=r"(r1) : "r"(a));
}
__device__ __forceinline__ void mma16816(float* d, uint32_t a0, uint32_t a1, uint32_t a2, uint32_t a3,
                                         uint32_t b0, uint32_t b1){
    asm volatile("mma.sync.aligned.m16n8k16.row.col.f32.bf16.bf16.f32 "
        "{%0,%1,%2,%3}, {%4,%5,%6,%7}, {%8,%9}, {%0,%1,%2,%3};"
        : "+f"(d[0]), "+f"(d[1]), "+f"(d[2]), "+f"(d[3])
        : "r"(a0), "r"(a1), "r"(a2), "r"(a3), "r"(b0), "r"(b1));
}
__device__ __forceinline__ void mma16816h(float* d, uint32_t a0, uint32_t a1, uint32_t a2, uint32_t a3,
                                          uint32_t b0, uint32_t b1){
    asm volatile("mma.sync.aligned.m16n8k16.row.col.f32.f16.f16.f32 "
        "{%0,%1,%2,%3}, {%4,%5,%6,%7}, {%8,%9}, {%0,%1,%2,%3};"
        : "+f"(d[0]), "+f"(d[1]), "+f"(d[2]), "+f"(d[3])
        : "r"(a0), "r"(a1), "r"(a2), "r"(a3), "r"(b0), "r"(b1));
}
__device__ __forceinline__ uint32_t cvtpackh(float hi, float lo){
    uint32_t r; asm("cvt.rn.f16x2.f32 %0, %1, %2;" : "=r"(r) : "f"(hi), "f"(lo)); return r;
}

// ---------------- device global scratch ----------------
__device__ float g_w3j[14][2197];
__device__ double g_psum[14][WCHUNK];
__device__ float g_M[8][3];
__device__ float g_rv[NB][NN][68];                 // 66 used
__device__ float g_ctx[NB][NN][68];                // 66 used
__device__ __nv_bfloat16 g_fqh[NB][NN][32];        // query feats hi (22 + feat22=1)
__device__ __nv_bfloat16 g_fql[NB][NN][32];        // query feats lo
__device__ __nv_bfloat16 g_fkh[NB][NN][32];        // key feats hi (22 + feat22=pb)
__device__ __nv_bfloat16 g_fkl[NB][NN][32];        // key feats lo
__device__ __half g_rvTh[NB][72][NN];              // transposed V fp16, row 66 = ones

__constant__ int c_VAL_L[6][3] = {{4,0,4},{4,2,4},{6,2,4},{4,2,6},{6,0,6},{6,2,6}};
__constant__ int c_OUT_L[8][3] = {{4,4,4},{4,6,4},{6,4,4},{6,6,4},{4,4,6},{4,6,6},{6,4,6},{6,6,6}};
__constant__ int c_OUT_OFF[8] = {0,729,1782,2835,4356,5409,6930,8451};
__constant__ int c_VAL_OFF[6] = {0,81,486,1071,1656,1825};
__constant__ int c_VAL_SZ[6]  = {81,405,585,585,169,845};
__constant__ int c_OUT_SZ[8]  = {729,1053,1053,1521,1053,1521,1521,2197};

// ---------------- init: Wigner 3j ----------------
__device__ double d_cg(int l1,int l2,int l3,int m1,int m2,int m3,const double* F){
    if (m1+m2 != m3) return 0.0;
    double pA = (2.0*l3+1.0)*F[l3+l1-l2]*F[l3-l1+l2]*F[l1+l2-l3]/F[l1+l2+l3+1];
    double pB = F[l3+m3]*F[l3-m3]*F[l1-m1]*F[l1+m1]*F[l2-m2]*F[l2+m2];
    double pref = sqrt(pA*pB);
    double s = 0.0;
    for (int k = 0; k <= l1+l2-l3; k++){
        int d0=k, d1=l1+l2-l3-k, d2=l1-m1-k, d3=l2+m2-k, d4=l3-l2+m1+k, d5=l3-l1-m2+k;
        if (d0<0||d1<0||d2<0||d3<0||d4<0||d5<0) continue;
        double den = F[d0]*F[d1]*F[d2]*F[d3]*F[d4]*F[d5];
        s += ((k&1)? -1.0:1.0)/den;
    }
    return pref*s;
}

__device__ void build_q(int l, double2* q){
    int L = 2*l+1;
    for (int i=0;i<L*L;i++) q[i] = make_double2(0.0,0.0);
    double rs2 = 1.0/sqrt(2.0);
    for (int m=-l;m<0;m++){
        q[(l+m)*L + (l-m)] = make_double2(rs2, 0.0);
        q[(l+m)*L + (l+m)] = make_double2(0.0, -rs2);
    }
    q[l*L+l] = make_double2(1.0,0.0);
    for (int m=1;m<=l;m++){
        double sg = (m&1)? -1.0 : 1.0;
        q[(l+m)*L + (l+m)] = make_double2(sg*rs2, 0.0);
        q[(l+m)*L + (l-m)] = make_double2(0.0, sg*rs2);
    }
    double ph = (l % 4 == 0) ? 1.0 : -1.0;
    for (int i=0;i<L*L;i++){ q[i].x *= ph; q[i].y *= ph; }
}

__global__ void k_init_w3j_a(){
    int t = blockIdx.x, chunk = blockIdx.y;
    int l1,l2,l3;
    if (t<6){ l1=c_VAL_L[t][0]; l2=c_VAL_L[t][1]; l3=c_VAL_L[t][2]; }
    else    { l1=c_OUT_L[t-6][0]; l2=c_OUT_L[t-6][1]; l3=c_OUT_L[t-6][2]; }
    int I=2*l1+1, J=2*l2+1, K=2*l3+1;
    int IJK = I*J*K;
    int len = (IJK + WCHUNK - 1)/WCHUNK;
    int lo = chunk*len, hi = min(lo+len, IJK);
    __shared__ double sF[24];
    __shared__ double2 sQ1[169], sQ2[169], sQ3[169];
    __shared__ double sRed[128];
    int tid = threadIdx.x;
    if (tid < 24){ double r=1.0; for (int i=2;i<=tid;i++) r*= (double)i; sF[tid]=r; }
    if (tid==0) build_q(l1,sQ1);
    if (tid==1) build_q(l2,sQ2);
    if (tid==2) build_q(l3,sQ3);
    __syncthreads();
    double ss = 0.0;
    for (int idx=lo+tid; idx<hi; idx+=blockDim.x){
        int j = idx/(J*K); int r = idx - j*J*K; int l = r/K; int n = r - l*K;
        int ia[2] = {j, 2*l1-j};   int ni = (ia[1]==ia[0])?1:2;
        int kb[2] = {l, 2*l2-l};   int nk = (kb[1]==kb[0])?1:2;
        int mc[2] = {n, 2*l3-n};   int nm = (mc[1]==mc[0])?1:2;
        double acc = 0.0;
        for (int a=0;a<ni;a++){
            int i = ia[a];
            double2 q1 = sQ1[i*I+j];
            if (q1.x==0.0 && q1.y==0.0) continue;
            for (int bq=0;bq<nk;bq++){
                int k2 = kb[bq];
                double2 q2 = sQ2[k2*J+l];
                if (q2.x==0.0 && q2.y==0.0) continue;
                double px = q1.x*q2.x - q1.y*q2.y;
                double py = q1.x*q2.y + q1.y*q2.x;
                for (int cq=0;cq<nm;cq++){
                    int m = mc[cq];
                    double2 q3 = sQ3[m*K+n];
                    if (q3.x==0.0 && q3.y==0.0) continue;
                    double cg = d_cg(l1,l2,l3, i-l1, k2-l2, m-l3, sF);
                    if (cg==0.0) continue;
                    acc += (px*q3.x + py*q3.y)*cg;
                }
            }
        }
        g_w3j[t][idx] = (float)acc;
        ss += acc*acc;
    }
    sRed[tid] = ss;
    __syncthreads();
    for (int s=64;s>0;s>>=1){ if (tid<s) sRed[tid]+=sRed[tid+s]; __syncthreads(); }
    if (tid==0) g_psum[t][chunk] = sRed[0];
}

__global__ void k_init_w3j_b(){
    int t = blockIdx.x;
    int l3 = (t<6)? c_VAL_L[t][2] : c_OUT_L[t-6][2];
    int K = 2*l3+1;
    int IJK;
    if (t<6){ int l1=c_VAL_L[t][0], l2=c_VAL_L[t][1]; IJK=(2*l1+1)*(2*l2+1)*K; }
    else    { int l1=c_OUT_L[t-6][0], l2=c_OUT_L[t-6][1]; IJK=(2*l1+1)*(2*l2+1)*K; }
    __shared__ float sScale;
    if (threadIdx.x==0){
        double nrm2 = 0.0;
        for (int c=0;c<WCHUNK;c++) nrm2 += g_psum[t][c];
        double sc = (t<6)? sqrt((double)K/(3.0*CCH)) : sqrt((double)K/(4.0*CCH*CCH));
        sScale = (float)(sc/sqrt(nrm2));
    }
    __syncthreads();
    float s = sScale;
    for (int idx=threadIdx.x; idx<IJK; idx+=blockDim.x)
        g_w3j[t][idx] *= s;
}

// ---------------- init: M[p][qq] ----------------
__global__ void k_init_small(const float* __restrict__ w_lin_in, const float* __restrict__ w_val,
                             const float* __restrict__ w_out, const float* __restrict__ w_lin_out){
    int tid = threadIdx.x;
    if (tid < 24){
        int p = tid/3, qq = tid - p*3;
        int l1o = c_OUT_L[p][0], l2o = c_OUT_L[p][1], l3o = c_OUT_L[p][2];
        const float* wli_p = w_lin_in + (l1o==4 ? 0 : 8);
        const float* wlo   = w_lin_out + (l3o==4 ? 0 : 8);
        int q = (l2o==4 ? 0 : 3) + qq;
        const float* wli_q = w_lin_in + (c_VAL_L[q][0]==4 ? 0 : 8);
        float m = 0.f;
        for (int v=0; v<8; v++){
            float cpv = 0.f;
            for (int u=0; u<8; u++){
                float wu = wli_p[u];
                const float* wo = w_out + ((p*8+u)*8+v)*8;
                for (int w=0; w<8; w++) cpv += wu * wo[w] * wlo[w];
            }
            float aqv = 0.f;
            for (int u=0; u<8; u++) aqv += wli_q[u]*w_val[(q*8+u)*8+v];
            m += cpv*aqv;
        }
        g_M[p][qq] = m * 0.35355339059327373f;
    }
}

// ---------------- prep: per-node bf16 hi/lo features, rv ----------------
__global__ void k_prep(const float* __restrict__ feat, const float* __restrict__ sh_lr,
                       const float* __restrict__ log_s, const float* __restrict__ pos_w,
                       const float* __restrict__ pos_b){
    __shared__ float sW[2670];
    __shared__ float sFt[8][22];
    __shared__ float sY[8][6];
    int tid = threadIdx.x, warp = tid>>5, lane = tid&31;
    for (int p=0;p<6;p++)
        for (int i=tid;i<c_VAL_SZ[p];i+=blockDim.x) sW[c_VAL_OFF[p]+i] = g_w3j[p][i];
    int node = blockIdx.x*8 + warp;
    int b = node >> 12, n = node & (NN-1);
    const float* f = feat + ((size_t)b*NN + n)*22;
    if (lane < 22) sFt[warp][lane] = f[lane];
    if (lane < 6)  sY[warp][lane]  = sh_lr[n*6+lane];
    __syncthreads();
    float n4=0.f, n6=0.f;
    #pragma unroll
    for (int d=0; d<9; d++){ float v=sFt[warp][d]; n4 += v*v; }
    #pragma unroll
    for (int d=9; d<22; d++){ float v=sFt[warp][d]; n6 += v*v; }
    float s4 = __expf(log_s[0]), s6 = __expf(log_s[1]);
    float r4 = sqrtf(s4)/fmaxf(sqrtf(n4), 1e-12f);
    float r6 = sqrtf(s6)/fmaxf(sqrtf(n6), 1e-12f);
    float pb = pos_b[0];
    #pragma unroll
    for (int j=0;j<6;j++) pb += sY[warp][j]*pos_w[j];
    float v;
    if (lane < 9)       v = sFt[warp][lane]*r4;
    else if (lane < 22) v = sFt[warp][lane]*r6;
    else                v = 0.f;
    float vq = (lane==22) ? 1.0f : v;
    float vk = (lane==22) ? pb   : v;
    {
        __nv_bfloat16 hq = __float2bfloat16(vq);
        g_fqh[b][n][lane] = hq;
        g_fql[b][n][lane] = __float2bfloat16(vq - __bfloat162float(hq));
        __nv_bfloat16 hk = __float2bfloat16(vk);
        g_fkh[b][n][lane] = hk;
        g_fkl[b][n][lane] = __float2bfloat16(vk - __bfloat162float(hk));
    }
    float* rv = &g_rv[b][n][0];
    for (int t=lane; t<68; t+=32){
        if (t >= 66){ rv[t] = 0.f; continue; }
        int p,k;
        if (t < 27){ p = t/9; k = t - p*9; } else { int u=t-27; p = 3 + u/13; k = u - (p-3)*13; }
        int l1 = c_VAL_L[p][0], l2 = c_VAL_L[p][1];
        int I = 2*l1+1, J = 2*l2+1, K = 2*c_VAL_L[p][2]+1;
        int foff = (l1==4)? 0 : 9;
        const float* w = sW + c_VAL_OFF[p];
        float r = 0.f;
        if (J == 1){
            float y0 = sY[warp][0];
            for (int i=0;i<I;i++) r += sFt[warp][foff+i]*y0*w[i*K+k];
        } else {
            for (int i=0;i<I;i++){
                float fi = sFt[warp][foff+i];
                #pragma unroll
                for (int j=0;j<5;j++) r += fi*sY[warp][1+j]*w[(i*5+j)*K+k];
            }
        }
        rv[t] = r;
    }
}

// ---------------- transpose rv -> fp16 rvT[72][NN], row 66 = ones ----------------
__global__ void k_trans(){
    __shared__ float sm[64][68];
    int b = blockIdx.y;
    int n0 = blockIdx.x*64;
    int tid = threadIdx.x;
    for (int i=tid; i<64*17; i+=256){
        int r = i/17, f4 = i%17;
        *(float4*)&sm[r][f4*4] = *(const float4*)&g_rv[b][n0+r][f4*4];
    }
    __syncthreads();
    for (int t=tid; t<72*64; t+=256){
        int d = t/64, nn = t%64;
        float v;
        if (d < 66) v = sm[nn][d];
        else if (d == 66) v = 1.0f;
        else v = 0.0f;
        g_rvTh[b][d][n0+nn] = __float2half(v);
    }
}

// ---------------- fused attention (q-tile 64, 128 threads, grid 256) ----------------
// Per-warp instruction stream identical to R11; only CTA geometry changed.
// SMEM layout (bytes from base):
//   Qhi [64][40] @ 0 (5120), Qlo @ 5120
//   K stage s: Khi [64][40] @ 10240+s*10240, Klo @ +5120
//   V stage s (fp16): [72][72] @ 30720+s*10368
#define ATT_SMEM 51456

__global__ void __launch_bounds__(128,2) k_attn(){
    extern __shared__ __align__(16) char smem[];
    uint32_t sb = s2u(smem);
    int b = blockIdx.y, qt = blockIdx.x;
    int tid = threadIdx.x, wid = tid>>5, lane = tid&31;
    int m0 = wid*16;

    auto loadQ = [&](){
        #pragma unroll
        for (int j=0;j<4;j++){
            int idx = tid + j*128;        // 512 = 2 planes * 64 rows * 4 segs
            int plane = idx>>8, rr = idx&255;
            int row = rr>>2, seg = rr&3;
            const __nv_bfloat16* src = plane ? &g_fql[b][qt*64+row][seg*8] : &g_fqh[b][qt*64+row][seg*8];
            cpasync16(sb + plane*5120 + row*80 + seg*16, src);
        }
    };
    auto loadK = [&](int c){
        uint32_t kb2 = sb + 10240 + (c&1)*10240;
        int kbase = c*64;
        #pragma unroll
        for (int j=0;j<4;j++){
            int idx = tid + j*128;        // 512 = 2 planes * 64 rows * 4 segs
            int plane = idx>>8, rr = idx&255;
            int row = rr>>2, seg = rr&3;
            const __nv_bfloat16* src = plane ? &g_fkl[b][kbase+row][seg*8] : &g_fkh[b][kbase+row][seg*8];
            cpasync16(kb2 + plane*5120 + row*80 + seg*16, src);
        }
    };
    auto loadV = [&](int c){
        uint32_t vb = sb + 30720 + (c&1)*10368;
        int kbase = c*64;
        #pragma unroll
        for (int j=0;j<5;j++){
            int idx = tid + j*128;        // 576 = 72 rows * 8 segs
            if (idx < 576){
                int row = idx>>3, seg = idx&7;
                cpasync16(vb + row*144 + seg*16, &g_rvTh[b][row][kbase+seg*8]);
            }
        }
    };

    loadQ(); loadK(0); loadV(0); CP_COMMIT();

    float acc[36];
    #pragma unroll
    for (int i=0;i<36;i++) acc[i]=0.f;

    uint32_t qh[2][4], ql[2][4];
    bool qloaded = false;

    for (int c=0; c<64; c++){
        if (c+1 < 64){ loadK(c+1); loadV(c+1); CP_COMMIT(); }
        if (c+1 < 64) asm volatile("cp.async.wait_group 1;" ::: "memory");
        else          asm volatile("cp.async.wait_group 0;" ::: "memory");
        __syncthreads();

        if (!qloaded){
            uint32_t aQh = sb +         ((m0 + (lane&15))*40 + (lane>>4)*8)*2;
            uint32_t aQl = sb + 5120u + ((m0 + (lane&15))*40 + (lane>>4)*8)*2;
            #pragma unroll
            for (int ks=0; ks<2; ks++){
                ldmx4(qh[ks][0],qh[ks][1],qh[ks][2],qh[ks][3], aQh + ks*32);
                ldmx4(ql[ks][0],ql[ks][1],ql[ks][2],ql[ks][3], aQl + ks*32);
            }
            qloaded = true;
        }

        uint32_t khi = sb + 10240 + (c&1)*10240;
        uint32_t klo = khi + 5120;
        uint32_t vh  = sb + 30720 + (c&1)*10368;
        uint32_t b4Off = (((lane&7) + ((lane>>3)&1)*8)*72 + (lane>>4)*8)*2;
        uint32_t b2Off = ((64 + (lane&7))*72 + ((lane>>3)&1)*8)*2;
        uint32_t kRow  = ((lane&7)*40 + ((lane>>3)&1)*8)*2;

        #pragma unroll
        for (int ks2=0; ks2<4; ks2++){
            // --- scores (3-term bf16, exact to ~2^-17) ---
            float S[8];
            #pragma unroll
            for (int i=0;i<8;i++) S[i]=0.f;
            #pragma unroll
            for (int half=0; half<2; half++){
                int nt = 2*ks2 + half;
                uint32_t kbase_off = nt*8*40*2;
                #pragma unroll
                for (int ks=0; ks<2; ks++){
                    uint32_t bh0,bh1, bl0,bl1;
                    ldmx2(bh0,bh1, khi + kbase_off + kRow + ks*32);
                    mma16816(S+half*4, qh[ks][0],qh[ks][1],qh[ks][2],qh[ks][3], bh0, bh1);
                    mma16816(S+half*4, ql[ks][0],ql[ks][1],ql[ks][2],ql[ks][3], bh0, bh1);
                    ldmx2(bl0,bl1, klo + kbase_off + kRow + ks*32);
                    mma16816(S+half*4, qh[ks][0],qh[ks][1],qh[ks][2],qh[ks][3], bl0, bl1);
                }
            }
            // --- exp + fp16 A-frag ---
            float p[8];
            #pragma unroll
            for (int i=0;i<8;i++) p[i] = __expf(S[i]);
            uint32_t ah[4];
            ah[0] = cvtpackh(p[1], p[0]);
            ah[1] = cvtpackh(p[3], p[2]);
            ah[2] = cvtpackh(p[5], p[4]);
            ah[3] = cvtpackh(p[7], p[6]);
            // --- P @ V (single-term fp16) ---
            uint32_t kofs = ks2*32;
            #pragma unroll
            for (int g=0; g<4; g++){
                uint32_t r0,r1,r2,r3;
                ldmx4(r0,r1,r2,r3, vh + b4Off + g*(16*72*2) + kofs);
                mma16816h(acc + (2*g)*4,   ah[0],ah[1],ah[2],ah[3], r0, r2);
                mma16816h(acc + (2*g+1)*4, ah[0],ah[1],ah[2],ah[3], r1, r3);
            }
            {
                uint32_t r0,r1;
                ldmx2(r0,r1, vh + b2Off + kofs);
                mma16816h(acc + 32, ah[0],ah[1],ah[2],ah[3], r0, r1);
            }
        }
        __syncthreads();
    }

    // epilogue: col 66 = row sum
    const unsigned FULL = 0xffffffffu;
    float s_hi = __shfl_sync(FULL, acc[32], (lane & 0x1c) + 1);
    float s_lo = __shfl_sync(FULL, acc[34], (lane & 0x1c) + 1);
    float inv_hi = 1.0f/s_hi, inv_lo = 1.0f/s_lo;
    int r0 = qt*64 + m0 + (lane>>2);
    int r1 = r0 + 8;
    int colb = 2*(lane&3);
    #pragma unroll
    for (int nt=0; nt<9; nt++){
        int j = nt*8 + colb;
        if (j < 66){
            float v0 = acc[nt*4+0]*inv_hi, v1 = acc[nt*4+1]*inv_hi;
            ull pk; asm("mov.b64 %0, {%1,%2};" : "=l"(pk) : "f"(v0), "f"(v1));
            *(ull*)&g_ctx[b][r0][j] = pk;
            float w0 = acc[nt*4+2]*inv_lo, w1 = acc[nt*4+3]*inv_lo;
            ull pk2; asm("mov.b64 %0, {%1,%2};" : "=l"(pk2) : "f"(w0), "f"(w1));
            *(ull*)&g_ctx[b][r1][j] = pk2;
        }
    }
}

// ---------------- out ----------------
template<int I,int J,int K>
__device__ __forceinline__ float path_term(const float* fp, const float* c0, const float* c1, const float* c2,
                                           float m0, float m1, float m2, const float* w, int k){
    float e[J];
    #pragma unroll
    for (int j=0;j<J;j++) e[j] = m0*c0[j] + m1*c1[j] + m2*c2[j];
    float d = 0.f;
    for (int i=0;i<I;i++){
        float fi = fp[i];
        #pragma unroll
        for (int j=0;j<J;j++) d += fi*e[j]*w[(i*J+j)*K+k];
    }
    return d;
}

__global__ void k_out(const float* __restrict__ feat, float* __restrict__ out){
    __shared__ float sW[10648];
    __shared__ float sFt[8][22];
    __shared__ float sC[8][66];
    int tid = threadIdx.x, warp = tid>>5, lane = tid&31;
    for (int p=0;p<8;p++)
        for (int i=tid;i<c_OUT_SZ[p];i+=blockDim.x) sW[c_OUT_OFF[p]+i] = g_w3j[6+p][i];
    int node = blockIdx.x*8 + warp;
    int b = node >> 12, n = node & (NN-1);
    if (lane < 22) sFt[warp][lane] = feat[((size_t)b*NN+n)*22 + lane];
    for (int t=lane; t<66; t+=32) sC[warp][t] = g_ctx[b][n][t];
    __syncthreads();
    if (lane < 22){
        const float* F = sFt[warp];
        const float* C = sC[warp];
        float d;
        if (lane < 9){
            int k = lane;
            d  = path_term<9 ,9 ,9>(F  , C   , C+9 , C+18, g_M[0][0],g_M[0][1],g_M[0][2], sW+c_OUT_OFF[0], k);
            d += path_term<9 ,13,9>(F  , C+27, C+40, C+53, g_M[1][0],g_M[1][1],g_M[1][2], sW+c_OUT_OFF[1], k);
            d += path_term<13,9 ,9>(F+9, C   , C+9 , C+18, g_M[2][0],g_M[2][1],g_M[2][2], sW+c_OUT_OFF[2], k);
            d += path_term<13,13,9>(F+9, C+27, C+40, C+53, g_M[3][0],g_M[3][1],g_M[3][2], sW+c_OUT_OFF[3], k);
        } else {
            int k = lane - 9;
            d  = path_term<9 ,9 ,13>(F  , C   , C+9 , C+18, g_M[4][0],g_M[4][1],g_M[4][2], sW+c_OUT_OFF[4], k);
            d += path_term<9 ,13,13>(F  , C+27, C+40, C+53, g_M[5][0],g_M[5][1],g_M[5][2], sW+c_OUT_OFF[5], k);
            d += path_term<13,9 ,13>(F+9, C   , C+9 , C+18, g_M[6][0],g_M[6][1],g_M[6][2], sW+c_OUT_OFF[6], k);
            d += path_term<13,13,13>(F+9, C+27, C+40, C+53, g_M[7][0],g_M[7][1],g_M[7][2], sW+c_OUT_OFF[7], k);
        }
        out[((size_t)b*NN+n)*22 + lane] = d;
    }
}

// ---------------- launch ----------------
extern "C" void kernel_launch(void* const* d_in, const int* in_sizes, int n_in,
                              void* d_out, int out_size){
    const float* feat      = (const float*)d_in[0];
    const float* sh_lr     = (const float*)d_in[1];
    const float* log_s     = (const float*)d_in[2];
    const float* pos_w     = (const float*)d_in[3];
    const float* pos_b     = (const float*)d_in[4];
    const float* w_lin_in  = (const float*)d_in[5];
    const float* w_val     = (const float*)d_in[6];
    const float* w_out     = (const float*)d_in[7];
    const float* w_lin_out = (const float*)d_in[8];
    float* out = (float*)d_out;

    cudaFuncSetAttribute(k_attn, cudaFuncAttributeMaxDynamicSharedMemorySize, ATT_SMEM);

    dim3 gi(14, WCHUNK);
    k_init_w3j_a<<<gi, 128>>>();
    k_init_w3j_b<<<14, 128>>>();
    k_init_small<<<1,32>>>(w_lin_in, w_val, w_out, w_lin_out);
    k_prep<<<(NB*NN)/8, 256>>>(feat, sh_lr, log_s, pos_w, pos_b);
    k_trans<<<dim3(NN/64, NB), 256>>>();
    k_attn<<<dim3(NN/64, NB), 128, ATT_SMEM>>>();
    k_out<<<(NB*NN)/8, 256>>>(feat, out);
}

// round 14
// speedup vs baseline: 1.7009x; 1.0773x over previous
#include <cuda_runtime.h>
#include <cuda_bf16.h>
#include <cuda_fp16.h>
#include <math.h>
#include <stdint.h>

#define NB 4
#define NN 4096
#define CCH 8
#define WCHUNK 64

typedef unsigned long long ull;

__device__ __forceinline__ uint32_t s2u(const void* p){
    uint32_t a;
    asm("{ .reg .u64 t; cvta.to.shared.u64 t, %1; cvt.u32.u64 %0, t; }" : "=r"(a) : "l"(p));
    return a;
}
__device__ __forceinline__ void cpasync16(uint32_t dst, const void* src){
    asm volatile("cp.async.cg.shared.global [%0], [%1], 16;" :: "r"(dst), "l"(src));
}
#define CP_COMMIT() asm volatile("cp.async.commit_group;" ::: "memory")

__device__ __forceinline__ void ldmx4(uint32_t& r0, uint32_t& r1, uint32_t& r2, uint32_t& r3, uint32_t a){
    asm volatile("ldmatrix.sync.aligned.m8n8.x4.shared.b16 {%0,%1,%2,%3}, [%4];"
        : "=r"(r0), "=r"(r1), "=r"(r2), "=r"(r3) : "r"(a));
}
__device__ __forceinline__ void ldmx2(uint32_t& r0, uint32_t& r1, uint32_t a){
    asm volatile("ldmatrix.sync.aligned.m8n8.x2.shared.b16 {%0,%1}, [%2];"
        : "=r"(r0), "=r"(r1) : "r"(a));
}
__device__ __forceinline__ void mma16816h(float* d, uint32_t a0, uint32_t a1, uint32_t a2, uint32_t a3,
                                          uint32_t b0, uint32_t b1){
    asm volatile("mma.sync.aligned.m16n8k16.row.col.f32.f16.f16.f32 "
        "{%0,%1,%2,%3}, {%4,%5,%6,%7}, {%8,%9}, {%0,%1,%2,%3};"
        : "+f"(d[0]), "+f"(d[1]), "+f"(d[2]), "+f"(d[3])
        : "r"(a0), "r"(a1), "r"(a2), "r"(a3), "r"(b0), "r"(b1));
}
__device__ __forceinline__ uint32_t cvtpackh(float hi, float lo){
    uint32_t r; asm("cvt.rn.f16x2.f32 %0, %1, %2;" : "=r"(r) : "f"(hi), "f"(lo)); return r;
}

// ---------------- device global scratch ----------------
__device__ float g_w3j[14][2197];
__device__ double g_psum[14][WCHUNK];
__device__ float g_M[8][3];
__device__ float g_rv[NB][NN][68];                 // 66 used
__device__ float g_ctx[NB][NN][68];                // 66 used
__device__ __half g_fq[NB][NN][32];                // query feats fp16 (22 + feat22=1)
__device__ __half g_fk[NB][NN][32];                // key feats fp16 (22 + feat22=pb)
__device__ __half g_rvTh[NB][72][NN];              // transposed V fp16, row 66 = ones

__constant__ int c_VAL_L[6][3] = {{4,0,4},{4,2,4},{6,2,4},{4,2,6},{6,0,6},{6,2,6}};
__constant__ int c_OUT_L[8][3] = {{4,4,4},{4,6,4},{6,4,4},{6,6,4},{4,4,6},{4,6,6},{6,4,6},{6,6,6}};
__constant__ int c_OUT_OFF[8] = {0,729,1782,2835,4356,5409,6930,8451};
__constant__ int c_VAL_OFF[6] = {0,81,486,1071,1656,1825};
__constant__ int c_VAL_SZ[6]  = {81,405,585,585,169,845};
__constant__ int c_OUT_SZ[8]  = {729,1053,1053,1521,1053,1521,1521,2197};

// ---------------- init: Wigner 3j ----------------
__device__ double d_cg(int l1,int l2,int l3,int m1,int m2,int m3,const double* F){
    if (m1+m2 != m3) return 0.0;
    double pA = (2.0*l3+1.0)*F[l3+l1-l2]*F[l3-l1+l2]*F[l1+l2-l3]/F[l1+l2+l3+1];
    double pB = F[l3+m3]*F[l3-m3]*F[l1-m1]*F[l1+m1]*F[l2-m2]*F[l2+m2];
    double pref = sqrt(pA*pB);
    double s = 0.0;
    for (int k = 0; k <= l1+l2-l3; k++){
        int d0=k, d1=l1+l2-l3-k, d2=l1-m1-k, d3=l2+m2-k, d4=l3-l2+m1+k, d5=l3-l1-m2+k;
        if (d0<0||d1<0||d2<0||d3<0||d4<0||d5<0) continue;
        double den = F[d0]*F[d1]*F[d2]*F[d3]*F[d4]*F[d5];
        s += ((k&1)? -1.0:1.0)/den;
    }
    return pref*s;
}

__device__ void build_q(int l, double2* q){
    int L = 2*l+1;
    for (int i=0;i<L*L;i++) q[i] = make_double2(0.0,0.0);
    double rs2 = 1.0/sqrt(2.0);
    for (int m=-l;m<0;m++){
        q[(l+m)*L + (l-m)] = make_double2(rs2, 0.0);
        q[(l+m)*L + (l+m)] = make_double2(0.0, -rs2);
    }
    q[l*L+l] = make_double2(1.0,0.0);
    for (int m=1;m<=l;m++){
        double sg = (m&1)? -1.0 : 1.0;
        q[(l+m)*L + (l+m)] = make_double2(sg*rs2, 0.0);
        q[(l+m)*L + (l-m)] = make_double2(0.0, sg*rs2);
    }
    double ph = (l % 4 == 0) ? 1.0 : -1.0;
    for (int i=0;i<L*L;i++){ q[i].x *= ph; q[i].y *= ph; }
}

__global__ void k_init_w3j_a(){
    int t = blockIdx.x, chunk = blockIdx.y;
    int l1,l2,l3;
    if (t<6){ l1=c_VAL_L[t][0]; l2=c_VAL_L[t][1]; l3=c_VAL_L[t][2]; }
    else    { l1=c_OUT_L[t-6][0]; l2=c_OUT_L[t-6][1]; l3=c_OUT_L[t-6][2]; }
    int I=2*l1+1, J=2*l2+1, K=2*l3+1;
    int IJK = I*J*K;
    int len = (IJK + WCHUNK - 1)/WCHUNK;
    int lo = chunk*len, hi = min(lo+len, IJK);
    __shared__ double sF[24];
    __shared__ double2 sQ1[169], sQ2[169], sQ3[169];
    __shared__ double sRed[128];
    int tid = threadIdx.x;
    if (tid < 24){ double r=1.0; for (int i=2;i<=tid;i++) r*= (double)i; sF[tid]=r; }
    if (tid==0) build_q(l1,sQ1);
    if (tid==1) build_q(l2,sQ2);
    if (tid==2) build_q(l3,sQ3);
    __syncthreads();
    double ss = 0.0;
    for (int idx=lo+tid; idx<hi; idx+=blockDim.x){
        int j = idx/(J*K); int r = idx - j*J*K; int l = r/K; int n = r - l*K;
        int ia[2] = {j, 2*l1-j};   int ni = (ia[1]==ia[0])?1:2;
        int kb[2] = {l, 2*l2-l};   int nk = (kb[1]==kb[0])?1:2;
        int mc[2] = {n, 2*l3-n};   int nm = (mc[1]==mc[0])?1:2;
        double acc = 0.0;
        for (int a=0;a<ni;a++){
            int i = ia[a];
            double2 q1 = sQ1[i*I+j];
            if (q1.x==0.0 && q1.y==0.0) continue;
            for (int bq=0;bq<nk;bq++){
                int k2 = kb[bq];
                double2 q2 = sQ2[k2*J+l];
                if (q2.x==0.0 && q2.y==0.0) continue;
                double px = q1.x*q2.x - q1.y*q2.y;
                double py = q1.x*q2.y + q1.y*q2.x;
                for (int cq=0;cq<nm;cq++){
                    int m = mc[cq];
                    double2 q3 = sQ3[m*K+n];
                    if (q3.x==0.0 && q3.y==0.0) continue;
                    double cg = d_cg(l1,l2,l3, i-l1, k2-l2, m-l3, sF);
                    if (cg==0.0) continue;
                    acc += (px*q3.x + py*q3.y)*cg;
                }
            }
        }
        g_w3j[t][idx] = (float)acc;
        ss += acc*acc;
    }
    sRed[tid] = ss;
    __syncthreads();
    for (int s=64;s>0;s>>=1){ if (tid<s) sRed[tid]+=sRed[tid+s]; __syncthreads(); }
    if (tid==0) g_psum[t][chunk] = sRed[0];
}

__global__ void k_init_w3j_b(){
    int t = blockIdx.x;
    int l3 = (t<6)? c_VAL_L[t][2] : c_OUT_L[t-6][2];
    int K = 2*l3+1;
    int IJK;
    if (t<6){ int l1=c_VAL_L[t][0], l2=c_VAL_L[t][1]; IJK=(2*l1+1)*(2*l2+1)*K; }
    else    { int l1=c_OUT_L[t-6][0], l2=c_OUT_L[t-6][1]; IJK=(2*l1+1)*(2*l2+1)*K; }
    __shared__ float sScale;
    if (threadIdx.x==0){
        double nrm2 = 0.0;
        for (int c=0;c<WCHUNK;c++) nrm2 += g_psum[t][c];
        double sc = (t<6)? sqrt((double)K/(3.0*CCH)) : sqrt((double)K/(4.0*CCH*CCH));
        sScale = (float)(sc/sqrt(nrm2));
    }
    __syncthreads();
    float s = sScale;
    for (int idx=threadIdx.x; idx<IJK; idx+=blockDim.x)
        g_w3j[t][idx] *= s;
}

// ---------------- init: M[p][qq] ----------------
__global__ void k_init_small(const float* __restrict__ w_lin_in, const float* __restrict__ w_val,
                             const float* __restrict__ w_out, const float* __restrict__ w_lin_out){
    int tid = threadIdx.x;
    if (tid < 24){
        int p = tid/3, qq = tid - p*3;
        int l1o = c_OUT_L[p][0], l2o = c_OUT_L[p][1], l3o = c_OUT_L[p][2];
        const float* wli_p = w_lin_in + (l1o==4 ? 0 : 8);
        const float* wlo   = w_lin_out + (l3o==4 ? 0 : 8);
        int q = (l2o==4 ? 0 : 3) + qq;
        const float* wli_q = w_lin_in + (c_VAL_L[q][0]==4 ? 0 : 8);
        float m = 0.f;
        for (int v=0; v<8; v++){
            float cpv = 0.f;
            for (int u=0; u<8; u++){
                float wu = wli_p[u];
                const float* wo = w_out + ((p*8+u)*8+v)*8;
                for (int w=0; w<8; w++) cpv += wu * wo[w] * wlo[w];
            }
            float aqv = 0.f;
            for (int u=0; u<8; u++) aqv += wli_q[u]*w_val[(q*8+u)*8+v];
            m += cpv*aqv;
        }
        g_M[p][qq] = m * 0.35355339059327373f;
    }
}

// ---------------- prep: per-node fp16 features, rv ----------------
__global__ void k_prep(const float* __restrict__ feat, const float* __restrict__ sh_lr,
                       const float* __restrict__ log_s, const float* __restrict__ pos_w,
                       const float* __restrict__ pos_b){
    __shared__ float sW[2670];
    __shared__ float sFt[8][22];
    __shared__ float sY[8][6];
    int tid = threadIdx.x, warp = tid>>5, lane = tid&31;
    for (int p=0;p<6;p++)
        for (int i=tid;i<c_VAL_SZ[p];i+=blockDim.x) sW[c_VAL_OFF[p]+i] = g_w3j[p][i];
    int node = blockIdx.x*8 + warp;
    int b = node >> 12, n = node & (NN-1);
    const float* f = feat + ((size_t)b*NN + n)*22;
    if (lane < 22) sFt[warp][lane] = f[lane];
    if (lane < 6)  sY[warp][lane]  = sh_lr[n*6+lane];
    __syncthreads();
    float n4=0.f, n6=0.f;
    #pragma unroll
    for (int d=0; d<9; d++){ float v=sFt[warp][d]; n4 += v*v; }
    #pragma unroll
    for (int d=9; d<22; d++){ float v=sFt[warp][d]; n6 += v*v; }
    float s4 = __expf(log_s[0]), s6 = __expf(log_s[1]);
    float r4 = sqrtf(s4)/fmaxf(sqrtf(n4), 1e-12f);
    float r6 = sqrtf(s6)/fmaxf(sqrtf(n6), 1e-12f);
    float pb = pos_b[0];
    #pragma unroll
    for (int j=0;j<6;j++) pb += sY[warp][j]*pos_w[j];
    float v;
    if (lane < 9)       v = sFt[warp][lane]*r4;
    else if (lane < 22) v = sFt[warp][lane]*r6;
    else                v = 0.f;
    float vq = (lane==22) ? 1.0f : v;
    float vk = (lane==22) ? pb   : v;
    g_fq[b][n][lane] = __float2half(vq);
    g_fk[b][n][lane] = __float2half(vk);
    float* rv = &g_rv[b][n][0];
    for (int t=lane; t<68; t+=32){
        if (t >= 66){ rv[t] = 0.f; continue; }
        int p,k;
        if (t < 27){ p = t/9; k = t - p*9; } else { int u=t-27; p = 3 + u/13; k = u - (p-3)*13; }
        int l1 = c_VAL_L[p][0], l2 = c_VAL_L[p][1];
        int I = 2*l1+1, J = 2*l2+1, K = 2*c_VAL_L[p][2]+1;
        int foff = (l1==4)? 0 : 9;
        const float* w = sW + c_VAL_OFF[p];
        float r = 0.f;
        if (J == 1){
            float y0 = sY[warp][0];
            for (int i=0;i<I;i++) r += sFt[warp][foff+i]*y0*w[i*K+k];
        } else {
            for (int i=0;i<I;i++){
                float fi = sFt[warp][foff+i];
                #pragma unroll
                for (int j=0;j<5;j++) r += fi*sY[warp][1+j]*w[(i*5+j)*K+k];
            }
        }
        rv[t] = r;
    }
}

// ---------------- transpose rv -> fp16 rvT[72][NN], row 66 = ones ----------------
__global__ void k_trans(){
    __shared__ float sm[64][68];
    int b = blockIdx.y;
    int n0 = blockIdx.x*64;
    int tid = threadIdx.x;
    for (int i=tid; i<64*17; i+=256){
        int r = i/17, f4 = i%17;
        *(float4*)&sm[r][f4*4] = *(const float4*)&g_rv[b][n0+r][f4*4];
    }
    __syncthreads();
    for (int t=tid; t<72*64; t+=256){
        int d = t/64, nn = t%64;
        float v;
        if (d < 66) v = sm[nn][d];
        else if (d == 66) v = 1.0f;
        else v = 0.0f;
        g_rvTh[b][d][n0+nn] = __float2half(v);
    }
}

// ---------------- fused attention (single-term fp16 scores + fp16 PV) ----------------
// SMEM layout (bytes from base):
//   Q  [64][40] fp16 @ 0 (5120)
//   K stage s: [64][40] fp16 @ 5120+s*5120
//   V stage s: [72][72] fp16 @ 15360+s*10368
#define ATT_SMEM 36096

__global__ void __launch_bounds__(128,2) k_attn(){
    extern __shared__ __align__(16) char smem[];
    uint32_t sb = s2u(smem);
    int b = blockIdx.y, qt = blockIdx.x;
    int tid = threadIdx.x, wid = tid>>5, lane = tid&31;
    int m0 = wid*16;

    auto loadQ = [&](){
        #pragma unroll
        for (int j=0;j<2;j++){
            int idx = tid + j*128;        // 256 = 64 rows * 4 segs
            int row = idx>>2, seg = idx&3;
            cpasync16(sb + row*80 + seg*16, &g_fq[b][qt*64+row][seg*8]);
        }
    };
    auto loadK = [&](int c){
        uint32_t kb2 = sb + 5120 + (c&1)*5120;
        int kbase = c*64;
        #pragma unroll
        for (int j=0;j<2;j++){
            int idx = tid + j*128;        // 256 = 64 rows * 4 segs
            int row = idx>>2, seg = idx&3;
            cpasync16(kb2 + row*80 + seg*16, &g_fk[b][kbase+row][seg*8]);
        }
    };
    auto loadV = [&](int c){
        uint32_t vb = sb + 15360 + (c&1)*10368;
        int kbase = c*64;
        #pragma unroll
        for (int j=0;j<5;j++){
            int idx = tid + j*128;        // 576 = 72 rows * 8 segs
            if (idx < 576){
                int row = idx>>3, seg = idx&7;
                cpasync16(vb + row*144 + seg*16, &g_rvTh[b][row][kbase+seg*8]);
            }
        }
    };

    loadQ(); loadK(0); loadV(0); CP_COMMIT();

    float acc[36];
    #pragma unroll
    for (int i=0;i<36;i++) acc[i]=0.f;

    uint32_t qh[2][4];
    bool qloaded = false;

    for (int c=0; c<64; c++){
        if (c+1 < 64){ loadK(c+1); loadV(c+1); CP_COMMIT(); }
        if (c+1 < 64) asm volatile("cp.async.wait_group 1;" ::: "memory");
        else          asm volatile("cp.async.wait_group 0;" ::: "memory");
        __syncthreads();

        if (!qloaded){
            uint32_t aQ = sb + ((m0 + (lane&15))*40 + (lane>>4)*8)*2;
            #pragma unroll
            for (int ks=0; ks<2; ks++)
                ldmx4(qh[ks][0],qh[ks][1],qh[ks][2],qh[ks][3], aQ + ks*32);
            qloaded = true;
        }

        uint32_t kh = sb + 5120 + (c&1)*5120;
        uint32_t vh = sb + 15360 + (c&1)*10368;
        uint32_t b4Off = (((lane&7) + ((lane>>3)&1)*8)*72 + (lane>>4)*8)*2;
        uint32_t b2Off = ((64 + (lane&7))*72 + ((lane>>3)&1)*8)*2;
        uint32_t kRow  = ((lane&7)*40 + ((lane>>3)&1)*8)*2;

        #pragma unroll
        for (int ks2=0; ks2<4; ks2++){
            // --- scores (single-term fp16) ---
            float S[8];
            #pragma unroll
            for (int i=0;i<8;i++) S[i]=0.f;
            #pragma unroll
            for (int half=0; half<2; half++){
                int nt = 2*ks2 + half;
                uint32_t kbase_off = nt*8*40*2;
                #pragma unroll
                for (int ks=0; ks<2; ks++){
                    uint32_t bh0,bh1;
                    ldmx2(bh0,bh1, kh + kbase_off + kRow + ks*32);
                    mma16816h(S+half*4, qh[ks][0],qh[ks][1],qh[ks][2],qh[ks][3], bh0, bh1);
                }
            }
            // --- exp + fp16 A-frag ---
            float p[8];
            #pragma unroll
            for (int i=0;i<8;i++) p[i] = __expf(S[i]);
            uint32_t ah[4];
            ah[0] = cvtpackh(p[1], p[0]);
            ah[1] = cvtpackh(p[3], p[2]);
            ah[2] = cvtpackh(p[5], p[4]);
            ah[3] = cvtpackh(p[7], p[6]);
            // --- P @ V (single-term fp16) ---
            uint32_t kofs = ks2*32;
            #pragma unroll
            for (int g=0; g<4; g++){
                uint32_t r0,r1,r2,r3;
                ldmx4(r0,r1,r2,r3, vh + b4Off + g*(16*72*2) + kofs);
                mma16816h(acc + (2*g)*4,   ah[0],ah[1],ah[2],ah[3], r0, r2);
                mma16816h(acc + (2*g+1)*4, ah[0],ah[1],ah[2],ah[3], r1, r3);
            }
            {
                uint32_t r0,r1;
                ldmx2(r0,r1, vh + b2Off + kofs);
                mma16816h(acc + 32, ah[0],ah[1],ah[2],ah[3], r0, r1);
            }
        }
        __syncthreads();
    }

    // epilogue: col 66 = row sum
    const unsigned FULL = 0xffffffffu;
    float s_hi = __shfl_sync(FULL, acc[32], (lane & 0x1c) + 1);
    float s_lo = __shfl_sync(FULL, acc[34], (lane & 0x1c) + 1);
    float inv_hi = 1.0f/s_hi, inv_lo = 1.0f/s_lo;
    int r0 = qt*64 + m0 + (lane>>2);
    int r1 = r0 + 8;
    int colb = 2*(lane&3);
    #pragma unroll
    for (int nt=0; nt<9; nt++){
        int j = nt*8 + colb;
        if (j < 66){
            float v0 = acc[nt*4+0]*inv_hi, v1 = acc[nt*4+1]*inv_hi;
            ull pk; asm("mov.b64 %0, {%1,%2};" : "=l"(pk) : "f"(v0), "f"(v1));
            *(ull*)&g_ctx[b][r0][j] = pk;
            float w0 = acc[nt*4+2]*inv_lo, w1 = acc[nt*4+3]*inv_lo;
            ull pk2; asm("mov.b64 %0, {%1,%2};" : "=l"(pk2) : "f"(w0), "f"(w1));
            *(ull*)&g_ctx[b][r1][j] = pk2;
        }
    }
}

// ---------------- out ----------------
template<int I,int J,int K>
__device__ __forceinline__ float path_term(const float* fp, const float* c0, const float* c1, const float* c2,
                                           float m0, float m1, float m2, const float* w, int k){
    float e[J];
    #pragma unroll
    for (int j=0;j<J;j++) e[j] = m0*c0[j] + m1*c1[j] + m2*c2[j];
    float d = 0.f;
    for (int i=0;i<I;i++){
        float fi = fp[i];
        #pragma unroll
        for (int j=0;j<J;j++) d += fi*e[j]*w[(i*J+j)*K+k];
    }
    return d;
}

__global__ void k_out(const float* __restrict__ feat, float* __restrict__ out){
    __shared__ float sW[10648];
    __shared__ float sFt[8][22];
    __shared__ float sC[8][66];
    int tid = threadIdx.x, warp = tid>>5, lane = tid&31;
    for (int p=0;p<8;p++)
        for (int i=tid;i<c_OUT_SZ[p];i+=blockDim.x) sW[c_OUT_OFF[p]+i] = g_w3j[6+p][i];
    int node = blockIdx.x*8 + warp;
    int b = node >> 12, n = node & (NN-1);
    if (lane < 22) sFt[warp][lane] = feat[((size_t)b*NN+n)*22 + lane];
    for (int t=lane; t<66; t+=32) sC[warp][t] = g_ctx[b][n][t];
    __syncthreads();
    if (lane < 22){
        const float* F = sFt[warp];
        const float* C = sC[warp];
        float d;
        if (lane < 9){
            int k = lane;
            d  = path_term<9 ,9 ,9>(F  , C   , C+9 , C+18, g_M[0][0],g_M[0][1],g_M[0][2], sW+c_OUT_OFF[0], k);
            d += path_term<9 ,13,9>(F  , C+27, C+40, C+53, g_M[1][0],g_M[1][1],g_M[1][2], sW+c_OUT_OFF[1], k);
            d += path_term<13,9 ,9>(F+9, C   , C+9 , C+18, g_M[2][0],g_M[2][1],g_M[2][2], sW+c_OUT_OFF[2], k);
            d += path_term<13,13,9>(F+9, C+27, C+40, C+53, g_M[3][0],g_M[3][1],g_M[3][2], sW+c_OUT_OFF[3], k);
        } else {
            int k = lane - 9;
            d  = path_term<9 ,9 ,13>(F  , C   , C+9 , C+18, g_M[4][0],g_M[4][1],g_M[4][2], sW+c_OUT_OFF[4], k);
            d += path_term<9 ,13,13>(F  , C+27, C+40, C+53, g_M[5][0],g_M[5][1],g_M[5][2], sW+c_OUT_OFF[5], k);
            d += path_term<13,9 ,13>(F+9, C   , C+9 , C+18, g_M[6][0],g_M[6][1],g_M[6][2], sW+c_OUT_OFF[6], k);
            d += path_term<13,13,13>(F+9, C+27, C+40, C+53, g_M[7][0],g_M[7][1],g_M[7][2], sW+c_OUT_OFF[7], k);
        }
        out[((size_t)b*NN+n)*22 + lane] = d;
    }
}

// ---------------- launch ----------------
extern "C" void kernel_launch(void* const* d_in, const int* in_sizes, int n_in,
                              void* d_out, int out_size){
    const float* feat      = (const float*)d_in[0];
    const float* sh_lr     = (const float*)d_in[1];
    const float* log_s     = (const float*)d_in[2];
    const float* pos_w     = (const float*)d_in[3];
    const float* pos_b     = (const float*)d_in[4];
    const float* w_lin_in  = (const float*)d_in[5];
    const float* w_val     = (const float*)d_in[6];
    const float* w_out     = (const float*)d_in[7];
    const float* w_lin_out = (const float*)d_in[8];
    float* out = (float*)d_out;

    cudaFuncSetAttribute(k_attn, cudaFuncAttributeMaxDynamicSharedMemorySize, ATT_SMEM);

    dim3 gi(14, WCHUNK);
    k_init_w3j_a<<<gi, 128>>>();
    k_init_w3j_b<<<14, 128>>>();
    k_init_small<<<1,32>>>(w_lin_in, w_val, w_out, w_lin_out);
    k_prep<<<(NB*NN)/8, 256>>>(feat, sh_lr, log_s, pos_w, pos_b);
    k_trans<<<dim3(NN/64, NB), 256>>>();
    k_attn<<<dim3(NN/64, NB), 128, ATT_SMEM>>>();
    k_out<<<(NB*NN)/8, 256>>>(feat, out);
}

// round 16
// speedup vs baseline: 1.7339x; 1.0194x over previous
#include <cuda_runtime.h>
#include <cuda_bf16.h>
#include <cuda_fp16.h>
#include <math.h>
#include <stdint.h>

#define NB 4
#define NN 4096
#define CCH 8
#define WCHUNK 64

typedef unsigned long long ull;

__device__ __forceinline__ uint32_t s2u(const void* p){
    uint32_t a;
    asm("{ .reg .u64 t; cvta.to.shared.u64 t, %1; cvt.u32.u64 %0, t; }" : "=r"(a) : "l"(p));
    return a;
}
__device__ __forceinline__ void cpasync16(uint32_t dst, const void* src){
    asm volatile("cp.async.cg.shared.global [%0], [%1], 16;" :: "r"(dst), "l"(src));
}
#define CP_COMMIT() asm volatile("cp.async.commit_group;" ::: "memory")

__device__ __forceinline__ void ldmx4(uint32_t& r0, uint32_t& r1, uint32_t& r2, uint32_t& r3, uint32_t a){
    asm volatile("ldmatrix.sync.aligned.m8n8.x4.shared.b16 {%0,%1,%2,%3}, [%4];"
        : "=r"(r0), "=r"(r1), "=r"(r2), "=r"(r3) : "r"(a));
}
__device__ __forceinline__ void ldmx2(uint32_t& r0, uint32_t& r1, uint32_t a){
    asm volatile("ldmatrix.sync.aligned.m8n8.x2.shared.b16 {%0,%1}, [%2];"
        : "=r"(r0), "=r"(r1) : "r"(a));
}
__device__ __forceinline__ void mma16816h(float* d, uint32_t a0, uint32_t a1, uint32_t a2, uint32_t a3,
                                          uint32_t b0, uint32_t b1){
    asm volatile("mma.sync.aligned.m16n8k16.row.col.f32.f16.f16.f32 "
        "{%0,%1,%2,%3}, {%4,%5,%6,%7}, {%8,%9}, {%0,%1,%2,%3};"
        : "+f"(d[0]), "+f"(d[1]), "+f"(d[2]), "+f"(d[3])
        : "r"(a0), "r"(a1), "r"(a2), "r"(a3), "r"(b0), "r"(b1));
}
__device__ __forceinline__ uint32_t cvtpackh(float hi, float lo){
    uint32_t r; asm("cvt.rn.f16x2.f32 %0, %1, %2;" : "=r"(r) : "f"(hi), "f"(lo)); return r;
}

// ---------------- device global scratch ----------------
__device__ float g_w3j[14][2197];
__device__ double g_psum[14][WCHUNK];
__device__ float g_M[8][3];
__device__ float g_ctx[NB][NN][68];                // 66 used
__device__ __half g_fq[NB][NN][32];                // query feats fp16 (22 + feat22=1)
__device__ __half g_fk[NB][NN][32];                // key feats fp16 (22 + feat22=pb)
__device__ __half g_rvTh[NB][72][NN];              // transposed V fp16, row 66 = ones,
                                                   // rows 67-71 stay zero-initialized

__constant__ int c_VAL_L[6][3] = {{4,0,4},{4,2,4},{6,2,4},{4,2,6},{6,0,6},{6,2,6}};
__constant__ int c_OUT_L[8][3] = {{4,4,4},{4,6,4},{6,4,4},{6,6,4},{4,4,6},{4,6,6},{6,4,6},{6,6,6}};
__constant__ int c_OUT_OFF[8] = {0,729,1782,2835,4356,5409,6930,8451};
__constant__ int c_VAL_OFF[6] = {0,81,486,1071,1656,1825};
__constant__ int c_VAL_SZ[6]  = {81,405,585,585,169,845};
__constant__ int c_OUT_SZ[8]  = {729,1053,1053,1521,1053,1521,1521,2197};

// ---------------- init: Wigner 3j ----------------
__device__ double d_cg(int l1,int l2,int l3,int m1,int m2,int m3,const double* F){
    if (m1+m2 != m3) return 0.0;
    double pA = (2.0*l3+1.0)*F[l3+l1-l2]*F[l3-l1+l2]*F[l1+l2-l3]/F[l1+l2+l3+1];
    double pB = F[l3+m3]*F[l3-m3]*F[l1-m1]*F[l1+m1]*F[l2-m2]*F[l2+m2];
    double pref = sqrt(pA*pB);
    double s = 0.0;
    for (int k = 0; k <= l1+l2-l3; k++){
        int d0=k, d1=l1+l2-l3-k, d2=l1-m1-k, d3=l2+m2-k, d4=l3-l2+m1+k, d5=l3-l1-m2+k;
        if (d0<0||d1<0||d2<0||d3<0||d4<0||d5<0) continue;
        double den = F[d0]*F[d1]*F[d2]*F[d3]*F[d4]*F[d5];
        s += ((k&1)? -1.0:1.0)/den;
    }
    return pref*s;
}

__device__ void build_q(int l, double2* q){
    int L = 2*l+1;
    for (int i=0;i<L*L;i++) q[i] = make_double2(0.0,0.0);
    double rs2 = 1.0/sqrt(2.0);
    for (int m=-l;m<0;m++){
        q[(l+m)*L + (l-m)] = make_double2(rs2, 0.0);
        q[(l+m)*L + (l+m)] = make_double2(0.0, -rs2);
    }
    q[l*L+l] = make_double2(1.0,0.0);
    for (int m=1;m<=l;m++){
        double sg = (m&1)? -1.0 : 1.0;
        q[(l+m)*L + (l+m)] = make_double2(sg*rs2, 0.0);
        q[(l+m)*L + (l-m)] = make_double2(0.0, sg*rs2);
    }
    double ph = (l % 4 == 0) ? 1.0 : -1.0;
    for (int i=0;i<L*L;i++){ q[i].x *= ph; q[i].y *= ph; }
}

__global__ void k_init_w3j_a(){
    int t = blockIdx.x, chunk = blockIdx.y;
    int l1,l2,l3;
    if (t<6){ l1=c_VAL_L[t][0]; l2=c_VAL_L[t][1]; l3=c_VAL_L[t][2]; }
    else    { l1=c_OUT_L[t-6][0]; l2=c_OUT_L[t-6][1]; l3=c_OUT_L[t-6][2]; }
    int I=2*l1+1, J=2*l2+1, K=2*l3+1;
    int IJK = I*J*K;
    int len = (IJK + WCHUNK - 1)/WCHUNK;
    int lo = chunk*len, hi = min(lo+len, IJK);
    __shared__ double sF[24];
    __shared__ double2 sQ1[169], sQ2[169], sQ3[169];
    __shared__ double sRed[128];
    int tid = threadIdx.x;
    if (tid < 24){ double r=1.0; for (int i=2;i<=tid;i++) r*= (double)i; sF[tid]=r; }
    if (tid==0) build_q(l1,sQ1);
    if (tid==1) build_q(l2,sQ2);
    if (tid==2) build_q(l3,sQ3);
    __syncthreads();
    double ss = 0.0;
    for (int idx=lo+tid; idx<hi; idx+=blockDim.x){
        int j = idx/(J*K); int r = idx - j*J*K; int l = r/K; int n = r - l*K;
        int ia[2] = {j, 2*l1-j};   int ni = (ia[1]==ia[0])?1:2;
        int kb[2] = {l, 2*l2-l};   int nk = (kb[1]==kb[0])?1:2;
        int mc[2] = {n, 2*l3-n};   int nm = (mc[1]==mc[0])?1:2;
        double acc = 0.0;
        for (int a=0;a<ni;a++){
            int i = ia[a];
            double2 q1 = sQ1[i*I+j];
            if (q1.x==0.0 && q1.y==0.0) continue;
            for (int bq=0;bq<nk;bq++){
                int k2 = kb[bq];
                double2 q2 = sQ2[k2*J+l];
                if (q2.x==0.0 && q2.y==0.0) continue;
                double px = q1.x*q2.x - q1.y*q2.y;
                double py = q1.x*q2.y + q1.y*q2.x;
                for (int cq=0;cq<nm;cq++){
                    int m = mc[cq];
                    double2 q3 = sQ3[m*K+n];
                    if (q3.x==0.0 && q3.y==0.0) continue;
                    double cg = d_cg(l1,l2,l3, i-l1, k2-l2, m-l3, sF);
                    if (cg==0.0) continue;
                    acc += (px*q3.x + py*q3.y)*cg;
                }
            }
        }
        g_w3j[t][idx] = (float)acc;
        ss += acc*acc;
    }
    sRed[tid] = ss;
    __syncthreads();
    for (int s=64;s>0;s>>=1){ if (tid<s) sRed[tid]+=sRed[tid+s]; __syncthreads(); }
    if (tid==0) g_psum[t][chunk] = sRed[0];
}

// merged: blocks 0-13 rescale w3j; block 14 computes M
__global__ void k_init_fin(const float* __restrict__ w_lin_in, const float* __restrict__ w_val,
                           const float* __restrict__ w_out, const float* __restrict__ w_lin_out){
    int t = blockIdx.x;
    if (t < 14){
        int l3 = (t<6)? c_VAL_L[t][2] : c_OUT_L[t-6][2];
        int K = 2*l3+1;
        int IJK;
        if (t<6){ int l1=c_VAL_L[t][0], l2=c_VAL_L[t][1]; IJK=(2*l1+1)*(2*l2+1)*K; }
        else    { int l1=c_OUT_L[t-6][0], l2=c_OUT_L[t-6][1]; IJK=(2*l1+1)*(2*l2+1)*K; }
        __shared__ float sScale;
        if (threadIdx.x==0){
            double nrm2 = 0.0;
            for (int c=0;c<WCHUNK;c++) nrm2 += g_psum[t][c];
            double sc = (t<6)? sqrt((double)K/(3.0*CCH)) : sqrt((double)K/(4.0*CCH*CCH));
            sScale = (float)(sc/sqrt(nrm2));
        }
        __syncthreads();
        float s = sScale;
        for (int idx=threadIdx.x; idx<IJK; idx+=blockDim.x)
            g_w3j[t][idx] *= s;
    } else {
        int tid = threadIdx.x;
        if (tid < 24){
            int p = tid/3, qq = tid - p*3;
            int l1o = c_OUT_L[p][0], l2o = c_OUT_L[p][1], l3o = c_OUT_L[p][2];
            const float* wli_p = w_lin_in + (l1o==4 ? 0 : 8);
            const float* wlo   = w_lin_out + (l3o==4 ? 0 : 8);
            int q = (l2o==4 ? 0 : 3) + qq;
            const float* wli_q = w_lin_in + (c_VAL_L[q][0]==4 ? 0 : 8);
            float m = 0.f;
            for (int v=0; v<8; v++){
                float cpv = 0.f;
                for (int u=0; u<8; u++){
                    float wu = wli_p[u];
                    const float* wo = w_out + ((p*8+u)*8+v)*8;
                    for (int w=0; w<8; w++) cpv += wu * wo[w] * wlo[w];
                }
                float aqv = 0.f;
                for (int u=0; u<8; u++) aqv += wli_q[u]*w_val[(q*8+u)*8+v];
                m += cpv*aqv;
            }
            g_M[p][qq] = m * 0.35355339059327373f;
        }
    }
}

// ---------------- prep: fp16 q/k features + rv -> g_rvTh (fused transpose) ----------------
__global__ void k_prep(const float* __restrict__ feat, const float* __restrict__ sh_lr,
                       const float* __restrict__ log_s, const float* __restrict__ pos_w,
                       const float* __restrict__ pos_b){
    __shared__ float sW[2670];
    __shared__ float sFt[8][22];
    __shared__ float sY[8][6];
    int tid = threadIdx.x, warp = tid>>5, lane = tid&31;
    for (int p=0;p<6;p++)
        for (int i=tid;i<c_VAL_SZ[p];i+=blockDim.x) sW[c_VAL_OFF[p]+i] = g_w3j[p][i];
    int node = blockIdx.x*8 + warp;
    int b = node >> 12, n = node & (NN-1);
    const float* f = feat + ((size_t)b*NN + n)*22;
    if (lane < 22) sFt[warp][lane] = f[lane];
    if (lane < 6)  sY[warp][lane]  = sh_lr[n*6+lane];
    __syncthreads();
    float n4=0.f, n6=0.f;
    #pragma unroll
    for (int d=0; d<9; d++){ float v=sFt[warp][d]; n4 += v*v; }
    #pragma unroll
    for (int d=9; d<22; d++){ float v=sFt[warp][d]; n6 += v*v; }
    float s4 = __expf(log_s[0]), s6 = __expf(log_s[1]);
    float r4 = sqrtf(s4)/fmaxf(sqrtf(n4), 1e-12f);
    float r6 = sqrtf(s6)/fmaxf(sqrtf(n6), 1e-12f);
    float pb = pos_b[0];
    #pragma unroll
    for (int j=0;j<6;j++) pb += sY[warp][j]*pos_w[j];
    float v;
    if (lane < 9)       v = sFt[warp][lane]*r4;
    else if (lane < 22) v = sFt[warp][lane]*r6;
    else                v = 0.f;
    float vq = (lane==22) ? 1.0f : v;
    float vk = (lane==22) ? pb   : v;
    g_fq[b][n][lane] = __float2half(vq);
    g_fk[b][n][lane] = __float2half(vk);
    // rv -> transposed fp16 V directly (rows 67-71 remain zero-initialized)
    for (int t=lane; t<67; t+=32){
        if (t == 66){ g_rvTh[b][66][n] = __float2half(1.0f); continue; }
        int p,k;
        if (t < 27){ p = t/9; k = t - p*9; } else { int u=t-27; p = 3 + u/13; k = u - (p-3)*13; }
        int l1 = c_VAL_L[p][0], l2 = c_VAL_L[p][1];
        int I = 2*l1+1, J = 2*l2+1, K = 2*c_VAL_L[p][2]+1;
        int foff = (l1==4)? 0 : 9;
        const float* w = sW + c_VAL_OFF[p];
        float r = 0.f;
        if (J == 1){
            float y0 = sY[warp][0];
            for (int i=0;i<I;i++) r += sFt[warp][foff+i]*y0*w[i*K+k];
        } else {
            for (int i=0;i<I;i++){
                float fi = sFt[warp][foff+i];
                #pragma unroll
                for (int j=0;j<5;j++) r += fi*sY[warp][1+j]*w[(i*5+j)*K+k];
            }
        }
        g_rvTh[b][t][n] = __float2half(r);
    }
}

// ---------------- fused attention (single-term fp16 scores + fp16 PV) ----------------
// SMEM layout (bytes from base):
//   Q  [64][40] fp16 @ 0 (5120)
//   K stage s: [64][40] fp16 @ 5120+s*5120
//   V stage s: [72][72] fp16 @ 15360+s*10368
#define ATT_SMEM 36096

__global__ void __launch_bounds__(128,2) k_attn(){
    extern __shared__ __align__(16) char smem[];
    uint32_t sb = s2u(smem);
    int b = blockIdx.y, qt = blockIdx.x;
    int tid = threadIdx.x, wid = tid>>5, lane = tid&31;
    int m0 = wid*16;

    auto loadQ = [&](){
        #pragma unroll
        for (int j=0;j<2;j++){
            int idx = tid + j*128;
            int row = idx>>2, seg = idx&3;
            cpasync16(sb + row*80 + seg*16, &g_fq[b][qt*64+row][seg*8]);
        }
    };
    auto loadK = [&](int c){
        uint32_t kb2 = sb + 5120 + (c&1)*5120;
        int kbase = c*64;
        #pragma unroll
        for (int j=0;j<2;j++){
            int idx = tid + j*128;
            int row = idx>>2, seg = idx&3;
            cpasync16(kb2 + row*80 + seg*16, &g_fk[b][kbase+row][seg*8]);
        }
    };
    auto loadV = [&](int c){
        uint32_t vb = sb + 15360 + (c&1)*10368;
        int kbase = c*64;
        #pragma unroll
        for (int j=0;j<5;j++){
            int idx = tid + j*128;
            if (idx < 576){
                int row = idx>>3, seg = idx&7;
                cpasync16(vb + row*144 + seg*16, &g_rvTh[b][row][kbase+seg*8]);
            }
        }
    };

    loadQ(); loadK(0); loadV(0); CP_COMMIT();

    float acc[36];
    #pragma unroll
    for (int i=0;i<36;i++) acc[i]=0.f;

    uint32_t qh[2][4];
    bool qloaded = false;

    for (int c=0; c<64; c++){
        if (c+1 < 64){ loadK(c+1); loadV(c+1); CP_COMMIT(); }
        if (c+1 < 64) asm volatile("cp.async.wait_group 1;" ::: "memory");
        else          asm volatile("cp.async.wait_group 0;" ::: "memory");
        __syncthreads();

        if (!qloaded){
            uint32_t aQ = sb + ((m0 + (lane&15))*40 + (lane>>4)*8)*2;
            #pragma unroll
            for (int ks=0; ks<2; ks++)
                ldmx4(qh[ks][0],qh[ks][1],qh[ks][2],qh[ks][3], aQ + ks*32);
            qloaded = true;
        }

        uint32_t kh = sb + 5120 + (c&1)*5120;
        uint32_t vh = sb + 15360 + (c&1)*10368;
        uint32_t b4Off = (((lane&7) + ((lane>>3)&1)*8)*72 + (lane>>4)*8)*2;
        uint32_t b2Off = ((64 + (lane&7))*72 + ((lane>>3)&1)*8)*2;
        uint32_t kRow  = ((lane&7)*40 + ((lane>>3)&1)*8)*2;

        #pragma unroll
        for (int ks2=0; ks2<4; ks2++){
            float S[8];
            #pragma unroll
            for (int i=0;i<8;i++) S[i]=0.f;
            #pragma unroll
            for (int half=0; half<2; half++){
                int nt = 2*ks2 + half;
                uint32_t kbase_off = nt*8*40*2;
                #pragma unroll
                for (int ks=0; ks<2; ks++){
                    uint32_t bh0,bh1;
                    ldmx2(bh0,bh1, kh + kbase_off + kRow + ks*32);
                    mma16816h(S+half*4, qh[ks][0],qh[ks][1],qh[ks][2],qh[ks][3], bh0, bh1);
                }
            }
            float p[8];
            #pragma unroll
            for (int i=0;i<8;i++) p[i] = __expf(S[i]);
            uint32_t ah[4];
            ah[0] = cvtpackh(p[1], p[0]);
            ah[1] = cvtpackh(p[3], p[2]);
            ah[2] = cvtpackh(p[5], p[4]);
            ah[3] = cvtpackh(p[7], p[6]);
            uint32_t kofs = ks2*32;
            #pragma unroll
            for (int g=0; g<4; g++){
                uint32_t r0,r1,r2,r3;
                ldmx4(r0,r1,r2,r3, vh + b4Off + g*(16*72*2) + kofs);
                mma16816h(acc + (2*g)*4,   ah[0],ah[1],ah[2],ah[3], r0, r2);
                mma16816h(acc + (2*g+1)*4, ah[0],ah[1],ah[2],ah[3], r1, r3);
            }
            {
                uint32_t r0,r1;
                ldmx2(r0,r1, vh + b2Off + kofs);
                mma16816h(acc + 32, ah[0],ah[1],ah[2],ah[3], r0, r1);
            }
        }
        __syncthreads();
    }

    const unsigned FULL = 0xffffffffu;
    float s_hi = __shfl_sync(FULL, acc[32], (lane & 0x1c) + 1);
    float s_lo = __shfl_sync(FULL, acc[34], (lane & 0x1c) + 1);
    float inv_hi = 1.0f/s_hi, inv_lo = 1.0f/s_lo;
    int r0 = qt*64 + m0 + (lane>>2);
    int r1 = r0 + 8;
    int colb = 2*(lane&3);
    #pragma unroll
    for (int nt=0; nt<9; nt++){
        int j = nt*8 + colb;
        if (j < 66){
            float v0 = acc[nt*4+0]*inv_hi, v1 = acc[nt*4+1]*inv_hi;
            ull pk; asm("mov.b64 %0, {%1,%2};" : "=l"(pk) : "f"(v0), "f"(v1));
            *(ull*)&g_ctx[b][r0][j] = pk;
            float w0 = acc[nt*4+2]*inv_lo, w1 = acc[nt*4+3]*inv_lo;
            ull pk2; asm("mov.b64 %0, {%1,%2};" : "=l"(pk2) : "f"(w0), "f"(w1));
            *(ull*)&g_ctx[b][r1][j] = pk2;
        }
    }
}

// ---------------- out ----------------
template<int I,int J,int K>
__device__ __forceinline__ float path_term(const float* fp, const float* c0, const float* c1, const float* c2,
                                           float m0, float m1, float m2, const float* w, int k){
    float e[J];
    #pragma unroll
    for (int j=0;j<J;j++) e[j] = m0*c0[j] + m1*c1[j] + m2*c2[j];
    float d = 0.f;
    for (int i=0;i<I;i++){
        float fi = fp[i];
        #pragma unroll
        for (int j=0;j<J;j++) d += fi*e[j]*w[(i*J+j)*K+k];
    }
    return d;
}

__global__ void k_out(const float* __restrict__ feat, float* __restrict__ out){
    __shared__ float sW[10648];
    __shared__ float sFt[8][22];
    __shared__ float sC[8][66];
    int tid = threadIdx.x, warp = tid>>5, lane = tid&31;
    for (int p=0;p<8;p++)
        for (int i=tid;i<c_OUT_SZ[p];i+=blockDim.x) sW[c_OUT_OFF[p]+i] = g_w3j[6+p][i];
    int node = blockIdx.x*8 + warp;
    int b = node >> 12, n = node & (NN-1);
    if (lane < 22) sFt[warp][lane] = feat[((size_t)b*NN+n)*22 + lane];
    for (int t=lane; t<66; t+=32) sC[warp][t] = g_ctx[b][n][t];
    __syncthreads();
    if (lane < 22){
        const float* F = sFt[warp];
        const float* C = sC[warp];
        float d;
        if (lane < 9){
            int k = lane;
            d  = path_term<9 ,9 ,9>(F  , C   , C+9 , C+18, g_M[0][0],g_M[0][1],g_M[0][2], sW+c_OUT_OFF[0], k);
            d += path_term<9 ,13,9>(F  , C+27, C+40, C+53, g_M[1][0],g_M[1][1],g_M[1][2], sW+c_OUT_OFF[1], k);
            d += path_term<13,9 ,9>(F+9, C   , C+9 , C+18, g_M[2][0],g_M[2][1],g_M[2][2], sW+c_OUT_OFF[2], k);
            d += path_term<13,13,9>(F+9, C+27, C+40, C+53, g_M[3][0],g_M[3][1],g_M[3][2], sW+c_OUT_OFF[3], k);
        } else {
            int k = lane - 9;
            d  = path_term<9 ,9 ,13>(F  , C   , C+9 , C+18, g_M[4][0],g_M[4][1],g_M[4][2], sW+c_OUT_OFF[4], k);
            d += path_term<9 ,13,13>(F  , C+27, C+40, C+53, g_M[5][0],g_M[5][1],g_M[5][2], sW+c_OUT_OFF[5], k);
            d += path_term<13,9 ,13>(F+9, C   , C+9 , C+18, g_M[6][0],g_M[6][1],g_M[6][2], sW+c_OUT_OFF[6], k);
            d += path_term<13,13,13>(F+9, C+27, C+40, C+53, g_M[7][0],g_M[7][1],g_M[7][2], sW+c_OUT_OFF[7], k);
        }
        out[((size_t)b*NN+n)*22 + lane] = d;
    }
}

// ---------------- launch ----------------
extern "C" void kernel_launch(void* const* d_in, const int* in_sizes, int n_in,
                              void* d_out, int out_size){
    const float* feat      = (const float*)d_in[0];
    const float* sh_lr     = (const float*)d_in[1];
    const float* log_s     = (const float*)d_in[2];
    const float* pos_w     = (const float*)d_in[3];
    const float* pos_b     = (const float*)d_in[4];
    const float* w_lin_in  = (const float*)d_in[5];
    const float* w_val     = (const float*)d_in[6];
    const float* w_out     = (const float*)d_in[7];
    const float* w_lin_out = (const float*)d_in[8];
    float* out = (float*)d_out;

    cudaFuncSetAttribute(k_attn, cudaFuncAttributeMaxDynamicSharedMemorySize, ATT_SMEM);

    dim3 gi(14, WCHUNK);
    k_init_w3j_a<<<gi, 128>>>();
    k_init_fin<<<15, 128>>>(w_lin_in, w_val, w_out, w_lin_out);
    k_prep<<<(NB*NN)/8, 256>>>(feat, sh_lr, log_s, pos_w, pos_b);
    k_attn<<<dim3(NN/64, NB), 128, ATT_SMEM>>>();
    k_out<<<(NB*NN)/8, 256>>>(feat, out);
}

// round 17
// speedup vs baseline: 1.9206x; 1.1077x over previous
#include <cuda_runtime.h>
#include <cuda_bf16.h>
#include <cuda_fp16.h>
#include <math.h>
#include <stdint.h>

#define NB 4
#define NN 4096
#define CCH 8
#define WCHUNK 64

typedef unsigned long long ull;

__device__ __forceinline__ uint32_t s2u(const void* p){
    uint32_t a;
    asm("{ .reg .u64 t; cvta.to.shared.u64 t, %1; cvt.u32.u64 %0, t; }" : "=r"(a) : "l"(p));
    return a;
}
__device__ __forceinline__ void cpasync16(uint32_t dst, const void* src){
    asm volatile("cp.async.cg.shared.global [%0], [%1], 16;" :: "r"(dst), "l"(src));
}
#define CP_COMMIT() asm volatile("cp.async.commit_group;" ::: "memory")

__device__ __forceinline__ void ldmx4(uint32_t& r0, uint32_t& r1, uint32_t& r2, uint32_t& r3, uint32_t a){
    asm volatile("ldmatrix.sync.aligned.m8n8.x4.shared.b16 {%0,%1,%2,%3}, [%4];"
        : "=r"(r0), "=r"(r1), "=r"(r2), "=r"(r3) : "r"(a));
}
__device__ __forceinline__ void ldmx2(uint32_t& r0, uint32_t& r1, uint32_t a){
    asm volatile("ldmatrix.sync.aligned.m8n8.x2.shared.b16 {%0,%1}, [%2];"
        : "=r"(r0), "=r"(r1) : "r"(a));
}
__device__ __forceinline__ void mma16816h(float* d, uint32_t a0, uint32_t a1, uint32_t a2, uint32_t a3,
                                          uint32_t b0, uint32_t b1){
    asm volatile("mma.sync.aligned.m16n8k16.row.col.f32.f16.f16.f32 "
        "{%0,%1,%2,%3}, {%4,%5,%6,%7}, {%8,%9}, {%0,%1,%2,%3};"
        : "+f"(d[0]), "+f"(d[1]), "+f"(d[2]), "+f"(d[3])
        : "r"(a0), "r"(a1), "r"(a2), "r"(a3), "r"(b0), "r"(b1));
}
__device__ __forceinline__ uint32_t cvtpackh(float hi, float lo){
    uint32_t r; asm("cvt.rn.f16x2.f32 %0, %1, %2;" : "=r"(r) : "f"(hi), "f"(lo)); return r;
}

// ---------------- device global scratch ----------------
__device__ float g_w3j[14][2197];
__device__ double g_psum[14][WCHUNK];
__device__ float g_M[8][3];
__device__ float g_ctx[NB][NN][68];                // 66 used
__device__ __half g_fq[NB][NN][32];                // query feats fp16 (22 + feat22=1)
__device__ __half g_fk[NB][NN][32];                // key feats fp16 (22 + feat22=pb)
__device__ __half g_rvTh[NB][72][NN];              // transposed V fp16, row 66 = ones,
                                                   // rows 67-71 stay zero-initialized

__constant__ int c_VAL_L[6][3] = {{4,0,4},{4,2,4},{6,2,4},{4,2,6},{6,0,6},{6,2,6}};
__constant__ int c_OUT_L[8][3] = {{4,4,4},{4,6,4},{6,4,4},{6,6,4},{4,4,6},{4,6,6},{6,4,6},{6,6,6}};
__constant__ int c_OUT_OFF[8] = {0,729,1782,2835,4356,5409,6930,8451};
__constant__ int c_VAL_OFF[6] = {0,81,486,1071,1656,1825};
__constant__ int c_VAL_SZ[6]  = {81,405,585,585,169,845};
__constant__ int c_OUT_SZ[8]  = {729,1053,1053,1521,1053,1521,1521,2197};

// ---------------- init: Wigner 3j (div-free, sqrt-free CG) ----------------
// pref = sqrt(pA) * sqF[l3+m3]*sqF[l3-m3]*sqF[l1-m1]*sqF[l1+m1]*sqF[l2-m2]*sqF[l2+m2]
// k-term = prod of inverse factorials. Mathematically identical to reference.
__device__ double d_cg_fast(int l1,int l2,int l3,int m1,int m2,int m3,
                            const double* sqF, const double* iF, double sqrtPA){
    if (m1+m2 != m3) return 0.0;
    double pref = sqrtPA * sqF[l3+m3]*sqF[l3-m3]*sqF[l1-m1]*sqF[l1+m1]*sqF[l2-m2]*sqF[l2+m2];
    double s = 0.0;
    for (int k = 0; k <= l1+l2-l3; k++){
        int d0=k, d1=l1+l2-l3-k, d2=l1-m1-k, d3=l2+m2-k, d4=l3-l2+m1+k, d5=l3-l1-m2+k;
        if (d0<0||d1<0||d2<0||d3<0||d4<0||d5<0) continue;
        double t = iF[d0]*iF[d1]*iF[d2]*iF[d3]*iF[d4]*iF[d5];
        s += (k&1)? -t : t;
    }
    return pref*s;
}

__device__ void build_q(int l, double2* q){
    int L = 2*l+1;
    for (int i=0;i<L*L;i++) q[i] = make_double2(0.0,0.0);
    double rs2 = 1.0/sqrt(2.0);
    for (int m=-l;m<0;m++){
        q[(l+m)*L + (l-m)] = make_double2(rs2, 0.0);
        q[(l+m)*L + (l+m)] = make_double2(0.0, -rs2);
    }
    q[l*L+l] = make_double2(1.0,0.0);
    for (int m=1;m<=l;m++){
        double sg = (m&1)? -1.0 : 1.0;
        q[(l+m)*L + (l+m)] = make_double2(sg*rs2, 0.0);
        q[(l+m)*L + (l-m)] = make_double2(0.0, sg*rs2);
    }
    double ph = (l % 4 == 0) ? 1.0 : -1.0;
    for (int i=0;i<L*L;i++){ q[i].x *= ph; q[i].y *= ph; }
}

__global__ void k_init_w3j_a(){
    int t = blockIdx.x, chunk = blockIdx.y;
    int l1,l2,l3;
    if (t<6){ l1=c_VAL_L[t][0]; l2=c_VAL_L[t][1]; l3=c_VAL_L[t][2]; }
    else    { l1=c_OUT_L[t-6][0]; l2=c_OUT_L[t-6][1]; l3=c_OUT_L[t-6][2]; }
    int I=2*l1+1, J=2*l2+1, K=2*l3+1;
    int IJK = I*J*K;
    int len = (IJK + WCHUNK - 1)/WCHUNK;
    int lo = chunk*len, hi = min(lo+len, IJK);
    __shared__ double sF[24];
    __shared__ double sIF[24];       // 1/F
    __shared__ double sSF[24];       // sqrt(F)
    __shared__ double sSqrtPA;
    __shared__ double2 sQ1[169], sQ2[169], sQ3[169];
    __shared__ double sRed[128];
    int tid = threadIdx.x;
    if (tid < 24){
        double r=1.0;
        for (int i=2;i<=tid;i++) r *= (double)i;
        sF[tid]  = r;
        sIF[tid] = 1.0/r;
        sSF[tid] = sqrt(r);
    }
    if (tid==0) build_q(l1,sQ1);
    if (tid==1) build_q(l2,sQ2);
    if (tid==2) build_q(l3,sQ3);
    __syncthreads();
    if (tid==0){
        double pA = (2.0*l3+1.0)*sF[l3+l1-l2]*sF[l3-l1+l2]*sF[l1+l2-l3]*sIF[l1+l2+l3+1];
        sSqrtPA = sqrt(pA);
    }
    __syncthreads();
    double sqrtPA = sSqrtPA;
    double ss = 0.0;
    for (int idx=lo+tid; idx<hi; idx+=blockDim.x){
        int j = idx/(J*K); int r = idx - j*J*K; int l = r/K; int n = r - l*K;
        int ia[2] = {j, 2*l1-j};   int ni = (ia[1]==ia[0])?1:2;
        int kb[2] = {l, 2*l2-l};   int nk = (kb[1]==kb[0])?1:2;
        int mc[2] = {n, 2*l3-n};   int nm = (mc[1]==mc[0])?1:2;
        double acc = 0.0;
        for (int a=0;a<ni;a++){
            int i = ia[a];
            double2 q1 = sQ1[i*I+j];
            if (q1.x==0.0 && q1.y==0.0) continue;
            for (int bq=0;bq<nk;bq++){
                int k2 = kb[bq];
                double2 q2 = sQ2[k2*J+l];
                if (q2.x==0.0 && q2.y==0.0) continue;
                double px = q1.x*q2.x - q1.y*q2.y;
                double py = q1.x*q2.y + q1.y*q2.x;
                for (int cq=0;cq<nm;cq++){
                    int m = mc[cq];
                    double2 q3 = sQ3[m*K+n];
                    if (q3.x==0.0 && q3.y==0.0) continue;
                    double cg = d_cg_fast(l1,l2,l3, i-l1, k2-l2, m-l3, sSF, sIF, sqrtPA);
                    if (cg==0.0) continue;
                    acc += (px*q3.x + py*q3.y)*cg;
                }
            }
        }
        g_w3j[t][idx] = (float)acc;
        ss += acc*acc;
    }
    sRed[tid] = ss;
    __syncthreads();
    for (int s=64;s>0;s>>=1){ if (tid<s) sRed[tid]+=sRed[tid+s]; __syncthreads(); }
    if (tid==0) g_psum[t][chunk] = sRed[0];
}

// merged: blocks 0-13 rescale w3j; block 14 computes M
__global__ void k_init_fin(const float* __restrict__ w_lin_in, const float* __restrict__ w_val,
                           const float* __restrict__ w_out, const float* __restrict__ w_lin_out){
    int t = blockIdx.x;
    if (t < 14){
        int l3 = (t<6)? c_VAL_L[t][2] : c_OUT_L[t-6][2];
        int K = 2*l3+1;
        int IJK;
        if (t<6){ int l1=c_VAL_L[t][0], l2=c_VAL_L[t][1]; IJK=(2*l1+1)*(2*l2+1)*K; }
        else    { int l1=c_OUT_L[t-6][0], l2=c_OUT_L[t-6][1]; IJK=(2*l1+1)*(2*l2+1)*K; }
        __shared__ float sScale;
        if (threadIdx.x==0){
            double nrm2 = 0.0;
            for (int c=0;c<WCHUNK;c++) nrm2 += g_psum[t][c];
            double sc = (t<6)? sqrt((double)K/(3.0*CCH)) : sqrt((double)K/(4.0*CCH*CCH));
            sScale = (float)(sc/sqrt(nrm2));
        }
        __syncthreads();
        float s = sScale;
        for (int idx=threadIdx.x; idx<IJK; idx+=blockDim.x)
            g_w3j[t][idx] *= s;
    } else {
        int tid = threadIdx.x;
        if (tid < 24){
            int p = tid/3, qq = tid - p*3;
            int l1o = c_OUT_L[p][0], l2o = c_OUT_L[p][1], l3o = c_OUT_L[p][2];
            const float* wli_p = w_lin_in + (l1o==4 ? 0 : 8);
            const float* wlo   = w_lin_out + (l3o==4 ? 0 : 8);
            int q = (l2o==4 ? 0 : 3) + qq;
            const float* wli_q = w_lin_in + (c_VAL_L[q][0]==4 ? 0 : 8);
            float m = 0.f;
            for (int v=0; v<8; v++){
                float cpv = 0.f;
                for (int u=0; u<8; u++){
                    float wu = wli_p[u];
                    const float* wo = w_out + ((p*8+u)*8+v)*8;
                    for (int w=0; w<8; w++) cpv += wu * wo[w] * wlo[w];
                }
                float aqv = 0.f;
                for (int u=0; u<8; u++) aqv += wli_q[u]*w_val[(q*8+u)*8+v];
                m += cpv*aqv;
            }
            g_M[p][qq] = m * 0.35355339059327373f;
        }
    }
}

// ---------------- prep: fp16 q/k features + rv -> g_rvTh (fused transpose) ----------------
__global__ void k_prep(const float* __restrict__ feat, const float* __restrict__ sh_lr,
                       const float* __restrict__ log_s, const float* __restrict__ pos_w,
                       const float* __restrict__ pos_b){
    __shared__ float sW[2670];
    __shared__ float sFt[8][22];
    __shared__ float sY[8][6];
    int tid = threadIdx.x, warp = tid>>5, lane = tid&31;
    for (int p=0;p<6;p++)
        for (int i=tid;i<c_VAL_SZ[p];i+=blockDim.x) sW[c_VAL_OFF[p]+i] = g_w3j[p][i];
    int node = blockIdx.x*8 + warp;
    int b = node >> 12, n = node & (NN-1);
    const float* f = feat + ((size_t)b*NN + n)*22;
    if (lane < 22) sFt[warp][lane] = f[lane];
    if (lane < 6)  sY[warp][lane]  = sh_lr[n*6+lane];
    __syncthreads();
    float n4=0.f, n6=0.f;
    #pragma unroll
    for (int d=0; d<9; d++){ float v=sFt[warp][d]; n4 += v*v; }
    #pragma unroll
    for (int d=9; d<22; d++){ float v=sFt[warp][d]; n6 += v*v; }
    float s4 = __expf(log_s[0]), s6 = __expf(log_s[1]);
    float r4 = sqrtf(s4)/fmaxf(sqrtf(n4), 1e-12f);
    float r6 = sqrtf(s6)/fmaxf(sqrtf(n6), 1e-12f);
    float pb = pos_b[0];
    #pragma unroll
    for (int j=0;j<6;j++) pb += sY[warp][j]*pos_w[j];
    float v;
    if (lane < 9)       v = sFt[warp][lane]*r4;
    else if (lane < 22) v = sFt[warp][lane]*r6;
    else                v = 0.f;
    float vq = (lane==22) ? 1.0f : v;
    float vk = (lane==22) ? pb   : v;
    g_fq[b][n][lane] = __float2half(vq);
    g_fk[b][n][lane] = __float2half(vk);
    // rv -> transposed fp16 V directly (rows 67-71 remain zero-initialized)
    for (int t=lane; t<67; t+=32){
        if (t == 66){ g_rvTh[b][66][n] = __float2half(1.0f); continue; }
        int p,k;
        if (t < 27){ p = t/9; k = t - p*9; } else { int u=t-27; p = 3 + u/13; k = u - (p-3)*13; }
        int l1 = c_VAL_L[p][0], l2 = c_VAL_L[p][1];
        int I = 2*l1+1, J = 2*l2+1, K = 2*c_VAL_L[p][2]+1;
        int foff = (l1==4)? 0 : 9;
        const float* w = sW + c_VAL_OFF[p];
        float r = 0.f;
        if (J == 1){
            float y0 = sY[warp][0];
            for (int i=0;i<I;i++) r += sFt[warp][foff+i]*y0*w[i*K+k];
        } else {
            for (int i=0;i<I;i++){
                float fi = sFt[warp][foff+i];
                #pragma unroll
                for (int j=0;j<5;j++) r += fi*sY[warp][1+j]*w[(i*5+j)*K+k];
            }
        }
        g_rvTh[b][t][n] = __float2half(r);
    }
}

// ---------------- fused attention (single-term fp16 scores + fp16 PV) ----------------
#define ATT_SMEM 36096

__global__ void __launch_bounds__(128,2) k_attn(){
    extern __shared__ __align__(16) char smem[];
    uint32_t sb = s2u(smem);
    int b = blockIdx.y, qt = blockIdx.x;
    int tid = threadIdx.x, wid = tid>>5, lane = tid&31;
    int m0 = wid*16;

    auto loadQ = [&](){
        #pragma unroll
        for (int j=0;j<2;j++){
            int idx = tid + j*128;
            int row = idx>>2, seg = idx&3;
            cpasync16(sb + row*80 + seg*16, &g_fq[b][qt*64+row][seg*8]);
        }
    };
    auto loadK = [&](int c){
        uint32_t kb2 = sb + 5120 + (c&1)*5120;
        int kbase = c*64;
        #pragma unroll
        for (int j=0;j<2;j++){
            int idx = tid + j*128;
            int row = idx>>2, seg = idx&3;
            cpasync16(kb2 + row*80 + seg*16, &g_fk[b][kbase+row][seg*8]);
        }
    };
    auto loadV = [&](int c){
        uint32_t vb = sb + 15360 + (c&1)*10368;
        int kbase = c*64;
        #pragma unroll
        for (int j=0;j<5;j++){
            int idx = tid + j*128;
            if (idx < 576){
                int row = idx>>3, seg = idx&7;
                cpasync16(vb + row*144 + seg*16, &g_rvTh[b][row][kbase+seg*8]);
            }
        }
    };

    loadQ(); loadK(0); loadV(0); CP_COMMIT();

    float acc[36];
    #pragma unroll
    for (int i=0;i<36;i++) acc[i]=0.f;

    uint32_t qh[2][4];
    bool qloaded = false;

    for (int c=0; c<64; c++){
        if (c+1 < 64){ loadK(c+1); loadV(c+1); CP_COMMIT(); }
        if (c+1 < 64) asm volatile("cp.async.wait_group 1;" ::: "memory");
        else          asm volatile("cp.async.wait_group 0;" ::: "memory");
        __syncthreads();

        if (!qloaded){
            uint32_t aQ = sb + ((m0 + (lane&15))*40 + (lane>>4)*8)*2;
            #pragma unroll
            for (int ks=0; ks<2; ks++)
                ldmx4(qh[ks][0],qh[ks][1],qh[ks][2],qh[ks][3], aQ + ks*32);
            qloaded = true;
        }

        uint32_t kh = sb + 5120 + (c&1)*5120;
        uint32_t vh = sb + 15360 + (c&1)*10368;
        uint32_t b4Off = (((lane&7) + ((lane>>3)&1)*8)*72 + (lane>>4)*8)*2;
        uint32_t b2Off = ((64 + (lane&7))*72 + ((lane>>3)&1)*8)*2;
        uint32_t kRow  = ((lane&7)*40 + ((lane>>3)&1)*8)*2;

        #pragma unroll
        for (int ks2=0; ks2<4; ks2++){
            float S[8];
            #pragma unroll
            for (int i=0;i<8;i++) S[i]=0.f;
            #pragma unroll
            for (int half=0; half<2; half++){
                int nt = 2*ks2 + half;
                uint32_t kbase_off = nt*8*40*2;
                #pragma unroll
                for (int ks=0; ks<2; ks++){
                    uint32_t bh0,bh1;
                    ldmx2(bh0,bh1, kh + kbase_off + kRow + ks*32);
                    mma16816h(S+half*4, qh[ks][0],qh[ks][1],qh[ks][2],qh[ks][3], bh0, bh1);
                }
            }
            float p[8];
            #pragma unroll
            for (int i=0;i<8;i++) p[i] = __expf(S[i]);
            uint32_t ah[4];
            ah[0] = cvtpackh(p[1], p[0]);
            ah[1] = cvtpackh(p[3], p[2]);
            ah[2] = cvtpackh(p[5], p[4]);
            ah[3] = cvtpackh(p[7], p[6]);
            uint32_t kofs = ks2*32;
            #pragma unroll
            for (int g=0; g<4; g++){
                uint32_t r0,r1,r2,r3;
                ldmx4(r0,r1,r2,r3, vh + b4Off + g*(16*72*2) + kofs);
                mma16816h(acc + (2*g)*4,   ah[0],ah[1],ah[2],ah[3], r0, r2);
                mma16816h(acc + (2*g+1)*4, ah[0],ah[1],ah[2],ah[3], r1, r3);
            }
            {
                uint32_t r0,r1;
                ldmx2(r0,r1, vh + b2Off + kofs);
                mma16816h(acc + 32, ah[0],ah[1],ah[2],ah[3], r0, r1);
            }
        }
        __syncthreads();
    }

    const unsigned FULL = 0xffffffffu;
    float s_hi = __shfl_sync(FULL, acc[32], (lane & 0x1c) + 1);
    float s_lo = __shfl_sync(FULL, acc[34], (lane & 0x1c) + 1);
    float inv_hi = 1.0f/s_hi, inv_lo = 1.0f/s_lo;
    int r0 = qt*64 + m0 + (lane>>2);
    int r1 = r0 + 8;
    int colb = 2*(lane&3);
    #pragma unroll
    for (int nt=0; nt<9; nt++){
        int j = nt*8 + colb;
        if (j < 66){
            float v0 = acc[nt*4+0]*inv_hi, v1 = acc[nt*4+1]*inv_hi;
            ull pk; asm("mov.b64 %0, {%1,%2};" : "=l"(pk) : "f"(v0), "f"(v1));
            *(ull*)&g_ctx[b][r0][j] = pk;
            float w0 = acc[nt*4+2]*inv_lo, w1 = acc[nt*4+3]*inv_lo;
            ull pk2; asm("mov.b64 %0, {%1,%2};" : "=l"(pk2) : "f"(w0), "f"(w1));
            *(ull*)&g_ctx[b][r1][j] = pk2;
        }
    }
}

// ---------------- out ----------------
template<int I,int J,int K>
__device__ __forceinline__ float path_term(const float* fp, const float* c0, const float* c1, const float* c2,
                                           float m0, float m1, float m2, const float* w, int k){
    float e[J];
    #pragma unroll
    for (int j=0;j<J;j++) e[j] = m0*c0[j] + m1*c1[j] + m2*c2[j];
    float d = 0.f;
    for (int i=0;i<I;i++){
        float fi = fp[i];
        #pragma unroll
        for (int j=0;j<J;j++) d += fi*e[j]*w[(i*J+j)*K+k];
    }
    return d;
}

__global__ void k_out(const float* __restrict__ feat, float* __restrict__ out){
    __shared__ float sW[10648];
    __shared__ float sFt[8][22];
    __shared__ float sC[8][66];
    int tid = threadIdx.x, warp = tid>>5, lane = tid&31;
    for (int p=0;p<8;p++)
        for (int i=tid;i<c_OUT_SZ[p];i+=blockDim.x) sW[c_OUT_OFF[p]+i] = g_w3j[6+p][i];
    int node = blockIdx.x*8 + warp;
    int b = node >> 12, n = node & (NN-1);
    if (lane < 22) sFt[warp][lane] = feat[((size_t)b*NN+n)*22 + lane];
    for (int t=lane; t<66; t+=32) sC[warp][t] = g_ctx[b][n][t];
    __syncthreads();
    if (lane < 22){
        const float* F = sFt[warp];
        const float* C = sC[warp];
        float d;
        if (lane < 9){
            int k = lane;
            d  = path_term<9 ,9 ,9>(F  , C   , C+9 , C+18, g_M[0][0],g_M[0][1],g_M[0][2], sW+c_OUT_OFF[0], k);
            d += path_term<9 ,13,9>(F  , C+27, C+40, C+53, g_M[1][0],g_M[1][1],g_M[1][2], sW+c_OUT_OFF[1], k);
            d += path_term<13,9 ,9>(F+9, C   , C+9 , C+18, g_M[2][0],g_M[2][1],g_M[2][2], sW+c_OUT_OFF[2], k);
            d += path_term<13,13,9>(F+9, C+27, C+40, C+53, g_M[3][0],g_M[3][1],g_M[3][2], sW+c_OUT_OFF[3], k);
        } else {
            int k = lane - 9;
            d  = path_term<9 ,9 ,13>(F  , C   , C+9 , C+18, g_M[4][0],g_M[4][1],g_M[4][2], sW+c_OUT_OFF[4], k);
            d += path_term<9 ,13,13>(F  , C+27, C+40, C+53, g_M[5][0],g_M[5][1],g_M[5][2], sW+c_OUT_OFF[5], k);
            d += path_term<13,9 ,13>(F+9, C   , C+9 , C+18, g_M[6][0],g_M[6][1],g_M[6][2], sW+c_OUT_OFF[6], k);
            d += path_term<13,13,13>(F+9, C+27, C+40, C+53, g_M[7][0],g_M[7][1],g_M[7][2], sW+c_OUT_OFF[7], k);
        }
        out[((size_t)b*NN+n)*22 + lane] = d;
    }
}

// ---------------- launch ----------------
extern "C" void kernel_launch(void* const* d_in, const int* in_sizes, int n_in,
                              void* d_out, int out_size){
    const float* feat      = (const float*)d_in[0];
    const float* sh_lr     = (const float*)d_in[1];
    const float* log_s     = (const float*)d_in[2];
    const float* pos_w     = (const float*)d_in[3];
    const float* pos_b     = (const float*)d_in[4];
    const float* w_lin_in  = (const float*)d_in[5];
    const float* w_val     = (const float*)d_in[6];
    const float* w_out     = (const float*)d_in[7];
    const float* w_lin_out = (const float*)d_in[8];
    float* out = (float*)d_out;

    cudaFuncSetAttribute(k_attn, cudaFuncAttributeMaxDynamicSharedMemorySize, ATT_SMEM);

    dim3 gi(14, WCHUNK);
    k_init_w3j_a<<<gi, 128>>>();
    k_init_fin<<<15, 128>>>(w_lin_in, w_val, w_out, w_lin_out);
    k_prep<<<(NB*NN)/8, 256>>>(feat, sh_lr, log_s, pos_w, pos_b);
    k_attn<<<dim3(NN/64, NB), 128, ATT_SMEM>>>();
    k_out<<<(NB*NN)/8, 256>>>(feat, out);
}